// round 1
// baseline (speedup 1.0000x reference)
#include <cuda_runtime.h>
#include <cuda_bf16.h>
#include <math.h>
#include <float.h>

// ---------------- problem constants ----------------
#define SEQ   2048
#define DIM   1024
#define DEPTH 4
#define HEADS 16
#define DH    64
#define FFD   4096
#define VOCAB 32000

// ---------------- scratch (static device globals; no runtime alloc) -------
__device__ float g_x   [SEQ * DIM];          // residual stream
__device__ float g_xn  [SEQ * DIM];          // rmsnorm output
__device__ float g_qkv [SEQ * 3 * DIM];      // qkv projections
__device__ float g_sc  [(size_t)HEADS * SEQ * SEQ]; // attention scores/probs (256MB)
__device__ float g_o   [SEQ * DIM];          // attention output
__device__ float g_ff  [SEQ * FFD];          // ff hidden

// ---------------- embed ----------------
__global__ void __launch_bounds__(256) embed_kernel(const int* __restrict__ tokens,
                                                    const float* __restrict__ emb,
                                                    float* __restrict__ x) {
    int idx = blockIdx.x * 256 + threadIdx.x;   // SEQ*DIM total
    int row = idx >> 10;
    int d   = idx & 1023;
    x[idx] = emb[(size_t)tokens[row] * DIM + d];
}

// ---------------- rmsnorm: y = x / max(||x||,1e-12) * sqrt(DIM) * gamma ----
__global__ void __launch_bounds__(256) rmsnorm_kernel(const float* __restrict__ x,
                                                      const float* __restrict__ gamma,
                                                      float* __restrict__ y) {
    int row = blockIdx.x;
    const float* xr = x + (size_t)row * DIM;
    float ss = 0.f;
    for (int i = threadIdx.x; i < DIM; i += 256) { float v = xr[i]; ss += v * v; }
    __shared__ float red[256];
    red[threadIdx.x] = ss;
    __syncthreads();
    for (int s = 128; s > 0; s >>= 1) {
        if (threadIdx.x < s) red[threadIdx.x] += red[threadIdx.x + s];
        __syncthreads();
    }
    float scale = 32.0f / fmaxf(sqrtf(red[0]), 1e-12f);   // sqrt(1024)=32
    float* yr = y + (size_t)row * DIM;
    for (int i = threadIdx.x; i < DIM; i += 256)
        yr[i] = xr[i] * scale * gamma[i];
}

// ---------------- rotary on q and k heads (in place in qkv) ----------------
__global__ void __launch_bounds__(256) rotary_kernel(float* __restrict__ qkv) {
    int idx = blockIdx.x * 256 + threadIdx.x;   // SEQ * 32heads * 32pairs
    int j    = idx & 31;           // pair index within head (dh/2 = 32)
    int head = (idx >> 5) & 31;    // heads 0..15 = q, 16..31 = k
    int pos  = idx >> 10;
    float inv = powf(10000.0f, -((float)(2 * j)) * (1.0f / 64.0f));
    float f = (float)pos * inv;
    float c = cosf(f), s = sinf(f);
    float* base = qkv + (size_t)pos * (3 * DIM) + head * DH;
    float x1 = base[j], x2 = base[j + 32];
    base[j]      = x1 * c - x2 * s;
    base[j + 32] = x2 * c + x1 * s;
}

// ---------------- generic fp32 GEMM: C = A[MxK] @ B[KxN] (+bias)(+gelu)(+residual=C) ----
// 128x128 tile, BK=16, 256 threads, 8x8 per thread
template<bool BIAS, bool RES, bool GELU>
__global__ void __launch_bounds__(256) sgemm_kernel(const float* __restrict__ A,
                                                    const float* __restrict__ B,
                                                    const float* __restrict__ bias,
                                                    float* __restrict__ C,
                                                    int M, int Nc, int K) {
    __shared__ float As[16][128];
    __shared__ float Bs[16][128];
    int tid = threadIdx.x;
    int tx = tid & 15, ty = tid >> 4;
    const float* Ab = A + (size_t)blockIdx.y * 128 * K;
    const float* Bb = B + (size_t)blockIdx.x * 128;
    float acc[8][8];
    #pragma unroll
    for (int r = 0; r < 8; r++)
        #pragma unroll
        for (int c = 0; c < 8; c++) acc[r][c] = 0.f;

    for (int k0 = 0; k0 < K; k0 += 16) {
        #pragma unroll
        for (int l = 0; l < 2; l++) {
            int i = tid + l * 256;               // float4 index, 512 total
            int m  = i >> 2;
            int kk = (i & 3) * 4;
            float4 v = *(const float4*)(Ab + (size_t)m * K + k0 + kk);
            As[kk + 0][m] = v.x; As[kk + 1][m] = v.y;
            As[kk + 2][m] = v.z; As[kk + 3][m] = v.w;
        }
        #pragma unroll
        for (int l = 0; l < 2; l++) {
            int i = tid + l * 256;
            int kk = i >> 5;
            int n  = (i & 31) * 4;
            *(float4*)(&Bs[kk][n]) = *(const float4*)(Bb + (size_t)(k0 + kk) * Nc + n);
        }
        __syncthreads();
        #pragma unroll
        for (int kk = 0; kk < 16; kk++) {
            float ra[8], rb[8];
            *(float4*)(ra)     = *(const float4*)(&As[kk][ty * 8]);
            *(float4*)(ra + 4) = *(const float4*)(&As[kk][ty * 8 + 4]);
            *(float4*)(rb)     = *(const float4*)(&Bs[kk][tx * 8]);
            *(float4*)(rb + 4) = *(const float4*)(&Bs[kk][tx * 8 + 4]);
            #pragma unroll
            for (int r = 0; r < 8; r++)
                #pragma unroll
                for (int c = 0; c < 8; c++)
                    acc[r][c] += ra[r] * rb[c];
        }
        __syncthreads();
    }

    int row0 = blockIdx.y * 128 + ty * 8;
    int col0 = blockIdx.x * 128 + tx * 8;
    #pragma unroll
    for (int r = 0; r < 8; r++) {
        size_t off = (size_t)(row0 + r) * Nc + col0;
        #pragma unroll
        for (int c = 0; c < 8; c++) {
            float val = acc[r][c];
            if (BIAS) val += bias[col0 + c];
            if (GELU) val = 0.5f * val * (1.0f + erff(val * 0.70710678118654752f));
            if (RES)  val += C[off + c];
            C[off + c] = val;
        }
    }
}

// ---------------- attention scores: S[h,i,j] = 0.125 * q_i . k_j (causal) ----
__global__ void __launch_bounds__(256) attn_scores_kernel(const float* __restrict__ qkv,
                                                          float* __restrict__ S) {
    int bc = blockIdx.x, br = blockIdx.y, h = blockIdx.z;
    if (bc > br) return;  // fully above diagonal, softmax never reads it
    __shared__ float Qs[64][64];   // [d][i]
    __shared__ float Ks[64][64];   // [d][j]
    int tid = threadIdx.x;
    const float* qb = qkv + (size_t)br * 64 * (3 * DIM) + h * DH;
    const float* kb = qkv + (size_t)bc * 64 * (3 * DIM) + (HEADS + h) * DH;
    #pragma unroll
    for (int l = 0; l < 4; l++) {
        int i = tid + l * 256;        // 1024 float4s
        int r  = i >> 4;
        int d4 = (i & 15) * 4;
        float4 v = *(const float4*)(qb + (size_t)r * (3 * DIM) + d4);
        Qs[d4 + 0][r] = v.x; Qs[d4 + 1][r] = v.y; Qs[d4 + 2][r] = v.z; Qs[d4 + 3][r] = v.w;
        float4 w = *(const float4*)(kb + (size_t)r * (3 * DIM) + d4);
        Ks[d4 + 0][r] = w.x; Ks[d4 + 1][r] = w.y; Ks[d4 + 2][r] = w.z; Ks[d4 + 3][r] = w.w;
    }
    __syncthreads();
    int tx = tid & 15, ty = tid >> 4;
    float acc[4][4];
    #pragma unroll
    for (int r = 0; r < 4; r++)
        #pragma unroll
        for (int c = 0; c < 4; c++) acc[r][c] = 0.f;
    #pragma unroll 4
    for (int d = 0; d < 64; d++) {
        float4 rq = *(const float4*)(&Qs[d][ty * 4]);
        float4 rk = *(const float4*)(&Ks[d][tx * 4]);
        float qa[4] = {rq.x, rq.y, rq.z, rq.w};
        float kaa[4] = {rk.x, rk.y, rk.z, rk.w};
        #pragma unroll
        for (int r = 0; r < 4; r++)
            #pragma unroll
            for (int c = 0; c < 4; c++)
                acc[r][c] += qa[r] * kaa[c];
    }
    float* Sh = S + (size_t)h * SEQ * SEQ;
    #pragma unroll
    for (int r = 0; r < 4; r++) {
        int gi = br * 64 + ty * 4 + r;
        #pragma unroll
        for (int c = 0; c < 4; c++) {
            int gj = bc * 64 + tx * 4 + c;
            float v = acc[r][c] * 0.125f;          // DH^-0.5
            if (gj > gi) v = -FLT_MAX;
            Sh[(size_t)gi * SEQ + gj] = v;
        }
    }
}

// ---------------- row softmax (causal; zero-fill masked tail) ----------------
__global__ void __launch_bounds__(256) softmax_kernel(float* __restrict__ S) {
    int i = blockIdx.x, h = blockIdx.y;
    float* row = S + ((size_t)h * SEQ + i) * SEQ;
    int len = i + 1;
    __shared__ float red[256];
    int tid = threadIdx.x;

    float m = -FLT_MAX;
    for (int j = tid; j < len; j += 256) m = fmaxf(m, row[j]);
    red[tid] = m;
    __syncthreads();
    for (int s = 128; s > 0; s >>= 1) {
        if (tid < s) red[tid] = fmaxf(red[tid], red[tid + s]);
        __syncthreads();
    }
    m = red[0];
    __syncthreads();

    float sum = 0.f;
    for (int j = tid; j < len; j += 256) sum += expf(row[j] - m);
    red[tid] = sum;
    __syncthreads();
    for (int s = 128; s > 0; s >>= 1) {
        if (tid < s) red[tid] += red[tid + s];
        __syncthreads();
    }
    float inv = 1.0f / red[0];

    for (int j = tid; j < SEQ; j += 256)
        row[j] = (j < len) ? expf(row[j] - m) * inv : 0.0f;
}

// ---------------- PV: O[:, h*64:(h+1)*64] = P_h @ V_h ----------------
__global__ void __launch_bounds__(256) attn_pv_kernel(const float* __restrict__ P,
                                                      const float* __restrict__ qkv,
                                                      float* __restrict__ O) {
    int br = blockIdx.x, h = blockIdx.z;
    __shared__ float Ps[32][65];   // [j][i], padded
    __shared__ float Vs[32][64];   // [j][d]
    int tid = threadIdx.x;
    int tx = tid & 15, ty = tid >> 4;
    float acc[4][4];
    #pragma unroll
    for (int r = 0; r < 4; r++)
        #pragma unroll
        for (int c = 0; c < 4; c++) acc[r][c] = 0.f;

    const float* Pb = P + ((size_t)h * SEQ + (size_t)br * 64) * SEQ;
    int jmax = (br + 1) * 64;      // causal: P is zero beyond the tile's max i
    for (int j0 = 0; j0 < jmax; j0 += 32) {
        #pragma unroll
        for (int l = 0; l < 8; l++) {
            int e = tid + l * 256;        // 2048 elements
            int il = e >> 5;
            int jj = e & 31;
            Ps[jj][il] = Pb[(size_t)il * SEQ + j0 + jj];
        }
        #pragma unroll
        for (int l = 0; l < 2; l++) {
            int e4 = tid + l * 256;       // 512 float4s
            int jj = e4 >> 4;
            int d  = (e4 & 15) * 4;
            *(float4*)(&Vs[jj][d]) =
                *(const float4*)(qkv + (size_t)(j0 + jj) * (3 * DIM) + (2 * HEADS + h) * DH + d);
        }
        __syncthreads();
        #pragma unroll 4
        for (int jj = 0; jj < 32; jj++) {
            float pr[4];
            #pragma unroll
            for (int r = 0; r < 4; r++) pr[r] = Ps[jj][ty * 4 + r];
            float4 rv = *(const float4*)(&Vs[jj][tx * 4]);
            float vv[4] = {rv.x, rv.y, rv.z, rv.w};
            #pragma unroll
            for (int r = 0; r < 4; r++)
                #pragma unroll
                for (int c = 0; c < 4; c++)
                    acc[r][c] += pr[r] * vv[c];
        }
        __syncthreads();
    }
    #pragma unroll
    for (int r = 0; r < 4; r++) {
        int gi = br * 64 + ty * 4 + r;
        #pragma unroll
        for (int c = 0; c < 4; c++)
            O[(size_t)gi * DIM + h * DH + tx * 4 + c] = acc[r][c];
    }
}

// ---------------- launch ----------------
extern "C" void kernel_launch(void* const* d_in, const int* in_sizes, int n_in,
                              void* d_out, int out_size) {
    const int*   tokens      = (const int*)  d_in[0];
    const float* emb         = (const float*)d_in[1];
    const float* gamma_attn  = (const float*)d_in[2];
    const float* w_qkv       = (const float*)d_in[3];
    const float* w_out       = (const float*)d_in[4];
    const float* gamma_ff    = (const float*)d_in[5];
    const float* w_ff1       = (const float*)d_in[6];
    const float* b_ff1       = (const float*)d_in[7];
    const float* w_ff2       = (const float*)d_in[8];
    const float* b_ff2       = (const float*)d_in[9];
    const float* gamma_final = (const float*)d_in[10];
    const float* w_logits    = (const float*)d_in[11];
    float* out = (float*)d_out;

    float *x, *xn, *qkv, *sc, *o, *ff;
    cudaGetSymbolAddress((void**)&x,   g_x);
    cudaGetSymbolAddress((void**)&xn,  g_xn);
    cudaGetSymbolAddress((void**)&qkv, g_qkv);
    cudaGetSymbolAddress((void**)&sc,  g_sc);
    cudaGetSymbolAddress((void**)&o,   g_o);
    cudaGetSymbolAddress((void**)&ff,  g_ff);

    embed_kernel<<<SEQ * DIM / 256, 256>>>(tokens, emb, x);

    for (int l = 0; l < DEPTH; l++) {
        // --- attention block ---
        rmsnorm_kernel<<<SEQ, 256>>>(x, gamma_attn + l * DIM, xn);
        sgemm_kernel<false, false, false><<<dim3(3 * DIM / 128, SEQ / 128), 256>>>(
            xn, w_qkv + (size_t)l * DIM * 3 * DIM, nullptr, qkv, SEQ, 3 * DIM, DIM);
        rotary_kernel<<<SEQ * 1024 / 256, 256>>>(qkv);
        attn_scores_kernel<<<dim3(SEQ / 64, SEQ / 64, HEADS), 256>>>(qkv, sc);
        softmax_kernel<<<dim3(SEQ, HEADS), 256>>>(sc);
        attn_pv_kernel<<<dim3(SEQ / 64, 1, HEADS), 256>>>(sc, qkv, o);
        sgemm_kernel<false, true, false><<<dim3(DIM / 128, SEQ / 128), 256>>>(
            o, w_out + (size_t)l * DIM * DIM, nullptr, x, SEQ, DIM, DIM);
        // --- feedforward block ---
        rmsnorm_kernel<<<SEQ, 256>>>(x, gamma_ff + l * DIM, xn);
        sgemm_kernel<true, false, true><<<dim3(FFD / 128, SEQ / 128), 256>>>(
            xn, w_ff1 + (size_t)l * DIM * FFD, b_ff1 + (size_t)l * FFD, ff, SEQ, FFD, DIM);
        sgemm_kernel<true, true, false><<<dim3(DIM / 128, SEQ / 128), 256>>>(
            ff, w_ff2 + (size_t)l * FFD * DIM, b_ff2 + (size_t)l * DIM, x, SEQ, DIM, FFD);
    }

    rmsnorm_kernel<<<SEQ, 256>>>(x, gamma_final, xn);
    sgemm_kernel<false, false, false><<<dim3(VOCAB / 128, SEQ / 128), 256>>>(
        xn, w_logits, nullptr, out, SEQ, VOCAB, DIM);
}

// round 2
// speedup vs baseline: 1.7121x; 1.7121x over previous
#include <cuda_runtime.h>
#include <cuda_bf16.h>
#include <math.h>
#include <float.h>
#include <stdint.h>

// ---------------- problem constants ----------------
#define SEQ   2048
#define DIM   1024
#define DEPTH 4
#define HEADS 16
#define DH    64
#define FFD   4096
#define VOCAB 32000

// ---------------- scratch (static device globals) ----------------
__device__ float g_x   [SEQ * DIM];                  // residual stream (fp32)
__device__ float g_qkv [SEQ * 3 * DIM];              // qkv projections (fp32)
__device__ float g_sc  [(size_t)HEADS * SEQ * SEQ];  // attention scores/probs
__device__ __nv_bfloat16 g_ab [SEQ * 3 * DIM];       // split activations (K=1024 GEMMs)
__device__ __nv_bfloat16 g_ab2[SEQ * 3 * FFD];       // split activations for ff2 (K=4096)
__device__ __nv_bfloat16 g_wb [249298944ull];        // all split weights

// weight offsets in g_wb (bf16 elements)
#define WB_QKV(l)  ((size_t)(l) * 9437184ull)
#define WB_OUT(l)  (37748736ull + (size_t)(l) * 3145728ull)
#define WB_FF1(l)  (50331648ull + (size_t)(l) * 12582912ull)
#define WB_FF2(l)  (100663296ull + (size_t)(l) * 12582912ull)
#define WB_LOGITS  150994944ull

// ---------------- helpers ----------------
__device__ __forceinline__ uint32_t smem_u32(const void* p) {
    return (uint32_t)__cvta_generic_to_shared(p);
}

// ---------------- weight split: w fp32[K,N] -> [Bhi ; Bhi ; Blo] bf16[3K,N] ----
__global__ void __launch_bounds__(256) convw_kernel(const float* __restrict__ w,
                                                    __nv_bfloat16* __restrict__ o,
                                                    long long KN) {
    long long idx = (long long)blockIdx.x * 256 + threadIdx.x;
    if (idx >= KN) return;
    float v = w[idx];
    __nv_bfloat16 hi = __float2bfloat16_rn(v);
    __nv_bfloat16 lo = __float2bfloat16_rn(v - __bfloat162float(hi));
    o[idx] = hi;
    o[idx + KN] = hi;
    o[idx + 2 * KN] = lo;
}

// ---------------- embed ----------------
__global__ void __launch_bounds__(256) embed_kernel(const int* __restrict__ tokens,
                                                    const float* __restrict__ emb,
                                                    float* __restrict__ x) {
    int idx = blockIdx.x * 256 + threadIdx.x;
    int row = idx >> 10;
    int d   = idx & 1023;
    x[idx] = emb[(size_t)tokens[row] * DIM + d];
}

// ---------------- rmsnorm + split: writes A' = [hi | lo | hi] (row stride 3*DIM) ----
__global__ void __launch_bounds__(256) rmsnorm_split_kernel(const float* __restrict__ x,
                                                            const float* __restrict__ gamma,
                                                            __nv_bfloat16* __restrict__ ab) {
    int row = blockIdx.x;
    const float* xr = x + (size_t)row * DIM;
    float ss = 0.f;
    for (int i = threadIdx.x; i < DIM; i += 256) { float v = xr[i]; ss += v * v; }
    __shared__ float red[256];
    red[threadIdx.x] = ss;
    __syncthreads();
    for (int s = 128; s > 0; s >>= 1) {
        if (threadIdx.x < s) red[threadIdx.x] += red[threadIdx.x + s];
        __syncthreads();
    }
    float scale = 32.0f / fmaxf(sqrtf(red[0]), 1e-12f);
    __nv_bfloat16* ar = ab + (size_t)row * (3 * DIM);
    for (int i = threadIdx.x; i < DIM; i += 256) {
        float v = xr[i] * scale * gamma[i];
        __nv_bfloat16 hi = __float2bfloat16_rn(v);
        __nv_bfloat16 lo = __float2bfloat16_rn(v - __bfloat162float(hi));
        ar[i] = hi;
        ar[DIM + i] = lo;
        ar[2 * DIM + i] = hi;
    }
}

// ---------------- rotary on q and k heads (in place in qkv, fp32) ----------------
__global__ void __launch_bounds__(256) rotary_kernel(float* __restrict__ qkv) {
    int idx = blockIdx.x * 256 + threadIdx.x;
    int j    = idx & 31;
    int head = (idx >> 5) & 31;
    int pos  = idx >> 10;
    float inv = powf(10000.0f, -((float)(2 * j)) * (1.0f / 64.0f));
    float f = (float)pos * inv;
    float c = cosf(f), s = sinf(f);
    float* base = qkv + (size_t)pos * (3 * DIM) + head * DH;
    float x1 = base[j], x2 = base[j + 32];
    base[j]      = x1 * c - x2 * s;
    base[j + 32] = x2 * c + x1 * s;
}

// ---------------- bf16 tensor-core GEMM: C[MxN] = A'[Mx(Kp)] @ B'[(Kp)xN] ----------
// 128x128x32 tiles, 8 warps (2m x 4n), warp tile 64x32, mma.sync m16n8k16 bf16.
// Epilogue flags: BIAS, RES (C += existing), GELU, SPLIT (write bf16 A'-format instead)
#define LDSM4(R0,R1,R2,R3,addr) \
    asm volatile("ldmatrix.sync.aligned.m8n8.x4.shared.b16 {%0,%1,%2,%3},[%4];" \
        : "=r"(R0),"=r"(R1),"=r"(R2),"=r"(R3) : "r"(addr))
#define LDSM4T(R0,R1,R2,R3,addr) \
    asm volatile("ldmatrix.sync.aligned.m8n8.x4.trans.shared.b16 {%0,%1,%2,%3},[%4];" \
        : "=r"(R0),"=r"(R1),"=r"(R2),"=r"(R3) : "r"(addr))
#define MMA16816(d,a,b0,b1) \
    asm volatile("mma.sync.aligned.m16n8k16.row.col.f32.bf16.bf16.f32 " \
        "{%0,%1,%2,%3},{%4,%5,%6,%7},{%8,%9},{%0,%1,%2,%3};" \
        : "+f"(d[0]),"+f"(d[1]),"+f"(d[2]),"+f"(d[3]) \
        : "r"(a[0]),"r"(a[1]),"r"(a[2]),"r"(a[3]),"r"(b0),"r"(b1))

template<bool BIAS, bool RES, bool GELU, bool SPLIT>
__global__ void __launch_bounds__(256)
bgemm_kernel(const __nv_bfloat16* __restrict__ A,
             const __nv_bfloat16* __restrict__ B,
             const float* __restrict__ bias,
             float* __restrict__ C,
             __nv_bfloat16* __restrict__ Cs,
             int M, int N, int Kp)
{
    __shared__ __align__(16) __nv_bfloat16 As[128 * 40];   // stride 40 (pad)
    __shared__ __align__(16) __nv_bfloat16 Bs[32 * 136];   // stride 136 (pad)

    int tid  = threadIdx.x;
    int lane = tid & 31;
    int warp = tid >> 5;
    int wm = warp >> 2;       // 0..1
    int wn = warp & 3;        // 0..3
    int bm = blockIdx.y * 128;
    int bn = blockIdx.x * 128;

    // global load assignments (2 uint4 each for A and B)
    int ra0 = tid >> 2;            // 0..63
    int ca0 = (tid & 3) * 8;       // 0,8,16,24
    int rb0 = tid >> 4;            // 0..15
    int cb  = (tid & 15) * 8;      // 0..120

    const char* gA0 = (const char*)(A + (size_t)(bm + ra0)      * Kp + ca0);
    const char* gA1 = (const char*)(A + (size_t)(bm + ra0 + 64) * Kp + ca0);
    const char* gB0 = (const char*)(B + (size_t)(rb0)      * N + bn + cb);
    const char* gB1 = (const char*)(B + (size_t)(rb0 + 16) * N + bn + cb);

    // ldmatrix base addresses
    uint32_t aLd = smem_u32(As) + (uint32_t)(((wm * 64 + (lane & 15)) * 40 + (lane >> 4) * 8) * 2);
    uint32_t bLd = smem_u32(Bs) + (uint32_t)(((lane & 15) * 136 + wn * 32 + (lane >> 4) * 8) * 2);

    float acc[4][4][4];
    #pragma unroll
    for (int i = 0; i < 4; i++)
        #pragma unroll
        for (int j = 0; j < 4; j++)
            #pragma unroll
            for (int k = 0; k < 4; k++) acc[i][j][k] = 0.f;

    uint4 pa0 = *(const uint4*)gA0;
    uint4 pa1 = *(const uint4*)gA1;
    uint4 pb0 = *(const uint4*)gB0;
    uint4 pb1 = *(const uint4*)gB1;

    int steps = Kp >> 5;  // Kp / 32
    for (int s = 0; s < steps; s++) {
        *(uint4*)&As[ra0 * 40 + ca0]        = pa0;
        *(uint4*)&As[(ra0 + 64) * 40 + ca0] = pa1;
        *(uint4*)&Bs[rb0 * 136 + cb]        = pb0;
        *(uint4*)&Bs[(rb0 + 16) * 136 + cb] = pb1;
        __syncthreads();

        if (s + 1 < steps) {
            gA0 += 64; gA1 += 64;                      // 32 bf16 along K
            gB0 += (size_t)64 * N; gB1 += (size_t)64 * N;  // 32 rows * N * 2B
            pa0 = *(const uint4*)gA0;
            pa1 = *(const uint4*)gA1;
            pb0 = *(const uint4*)gB0;
            pb1 = *(const uint4*)gB1;
        }

        #pragma unroll
        for (int kk = 0; kk < 2; kk++) {
            uint32_t af[4][4], bf[2][4];
            #pragma unroll
            for (int mt = 0; mt < 4; mt++) {
                uint32_t addr = aLd + mt * (16 * 40 * 2) + kk * 32;
                LDSM4(af[mt][0], af[mt][1], af[mt][2], af[mt][3], addr);
            }
            #pragma unroll
            for (int p = 0; p < 2; p++) {
                uint32_t addr = bLd + p * 32 + kk * (16 * 136 * 2);
                LDSM4T(bf[p][0], bf[p][1], bf[p][2], bf[p][3], addr);
            }
            #pragma unroll
            for (int mt = 0; mt < 4; mt++) {
                #pragma unroll
                for (int nt = 0; nt < 4; nt++) {
                    uint32_t b0 = bf[nt >> 1][(nt & 1) * 2];
                    uint32_t b1 = bf[nt >> 1][(nt & 1) * 2 + 1];
                    MMA16816(acc[mt][nt], af[mt], b0, b1);
                }
            }
        }
        __syncthreads();
    }

    // epilogue
    int row0 = bm + wm * 64;
    int col0 = bn + wn * 32;
    #pragma unroll
    for (int mt = 0; mt < 4; mt++) {
        #pragma unroll
        for (int nt = 0; nt < 4; nt++) {
            int r = row0 + mt * 16 + (lane >> 2);
            int c = col0 + nt * 8 + (lane & 3) * 2;
            #pragma unroll
            for (int half = 0; half < 2; half++) {
                int rr = r + half * 8;
                #pragma unroll
                for (int e = 0; e < 2; e++) {
                    float val = acc[mt][nt][half * 2 + e];
                    int cc = c + e;
                    if (BIAS) val += bias[cc];
                    if (GELU) val = 0.5f * val * (1.0f + erff(val * 0.70710678118654752f));
                    if (SPLIT) {
                        __nv_bfloat16 hi = __float2bfloat16_rn(val);
                        __nv_bfloat16 lo = __float2bfloat16_rn(val - __bfloat162float(hi));
                        size_t base = (size_t)rr * (3 * (size_t)N);
                        Cs[base + cc] = hi;
                        Cs[base + N + cc] = lo;
                        Cs[base + 2 * (size_t)N + cc] = hi;
                    } else {
                        size_t off = (size_t)rr * N + cc;
                        if (RES) val += C[off];
                        C[off] = val;
                    }
                }
            }
        }
    }
}

// ---------------- attention scores: S[h,i,j] = 0.125 * q_i . k_j (causal) ----
__global__ void __launch_bounds__(256) attn_scores_kernel(const float* __restrict__ qkv,
                                                          float* __restrict__ S) {
    int bc = blockIdx.x, br = blockIdx.y, h = blockIdx.z;
    if (bc > br) return;
    __shared__ float Qs[64][64];
    __shared__ float Ks[64][64];
    int tid = threadIdx.x;
    const float* qb = qkv + (size_t)br * 64 * (3 * DIM) + h * DH;
    const float* kb = qkv + (size_t)bc * 64 * (3 * DIM) + (HEADS + h) * DH;
    #pragma unroll
    for (int l = 0; l < 4; l++) {
        int i = tid + l * 256;
        int r  = i >> 4;
        int d4 = (i & 15) * 4;
        float4 v = *(const float4*)(qb + (size_t)r * (3 * DIM) + d4);
        Qs[d4 + 0][r] = v.x; Qs[d4 + 1][r] = v.y; Qs[d4 + 2][r] = v.z; Qs[d4 + 3][r] = v.w;
        float4 w = *(const float4*)(kb + (size_t)r * (3 * DIM) + d4);
        Ks[d4 + 0][r] = w.x; Ks[d4 + 1][r] = w.y; Ks[d4 + 2][r] = w.z; Ks[d4 + 3][r] = w.w;
    }
    __syncthreads();
    int tx = tid & 15, ty = tid >> 4;
    float acc[4][4];
    #pragma unroll
    for (int r = 0; r < 4; r++)
        #pragma unroll
        for (int c = 0; c < 4; c++) acc[r][c] = 0.f;
    #pragma unroll 4
    for (int d = 0; d < 64; d++) {
        float4 rq = *(const float4*)(&Qs[d][ty * 4]);
        float4 rk = *(const float4*)(&Ks[d][tx * 4]);
        float qa[4] = {rq.x, rq.y, rq.z, rq.w};
        float ka[4] = {rk.x, rk.y, rk.z, rk.w};
        #pragma unroll
        for (int r = 0; r < 4; r++)
            #pragma unroll
            for (int c = 0; c < 4; c++)
                acc[r][c] += qa[r] * ka[c];
    }
    float* Sh = S + (size_t)h * SEQ * SEQ;
    #pragma unroll
    for (int r = 0; r < 4; r++) {
        int gi = br * 64 + ty * 4 + r;
        #pragma unroll
        for (int c = 0; c < 4; c++) {
            int gj = bc * 64 + tx * 4 + c;
            float v = acc[r][c] * 0.125f;
            if (gj > gi) v = -FLT_MAX;
            Sh[(size_t)gi * SEQ + gj] = v;
        }
    }
}

// ---------------- row softmax (causal; zero-fill masked tail) ----------------
__global__ void __launch_bounds__(256) softmax_kernel(float* __restrict__ S) {
    int i = blockIdx.x, h = blockIdx.y;
    float* row = S + ((size_t)h * SEQ + i) * SEQ;
    int len = i + 1;
    __shared__ float red[256];
    int tid = threadIdx.x;

    float m = -FLT_MAX;
    for (int j = tid; j < len; j += 256) m = fmaxf(m, row[j]);
    red[tid] = m;
    __syncthreads();
    for (int s = 128; s > 0; s >>= 1) {
        if (tid < s) red[tid] = fmaxf(red[tid], red[tid + s]);
        __syncthreads();
    }
    m = red[0];
    __syncthreads();

    float sum = 0.f;
    for (int j = tid; j < len; j += 256) sum += expf(row[j] - m);
    red[tid] = sum;
    __syncthreads();
    for (int s = 128; s > 0; s >>= 1) {
        if (tid < s) red[tid] += red[tid + s];
        __syncthreads();
    }
    float inv = 1.0f / red[0];

    for (int j = tid; j < SEQ; j += 256)
        row[j] = (j < len) ? expf(row[j] - m) * inv : 0.0f;
}

// ---------------- PV: writes split-bf16 A' rows for the out-projection ----------
__global__ void __launch_bounds__(256) attn_pv_kernel(const float* __restrict__ P,
                                                      const float* __restrict__ qkv,
                                                      __nv_bfloat16* __restrict__ ab) {
    int br = blockIdx.x, h = blockIdx.z;
    __shared__ float Ps[32][65];
    __shared__ float Vs[32][64];
    int tid = threadIdx.x;
    int tx = tid & 15, ty = tid >> 4;
    float acc[4][4];
    #pragma unroll
    for (int r = 0; r < 4; r++)
        #pragma unroll
        for (int c = 0; c < 4; c++) acc[r][c] = 0.f;

    const float* Pb = P + ((size_t)h * SEQ + (size_t)br * 64) * SEQ;
    int jmax = (br + 1) * 64;
    for (int j0 = 0; j0 < jmax; j0 += 32) {
        #pragma unroll
        for (int l = 0; l < 8; l++) {
            int e = tid + l * 256;
            int il = e >> 5;
            int jj = e & 31;
            Ps[jj][il] = Pb[(size_t)il * SEQ + j0 + jj];
        }
        #pragma unroll
        for (int l = 0; l < 2; l++) {
            int e4 = tid + l * 256;
            int jj = e4 >> 4;
            int d  = (e4 & 15) * 4;
            *(float4*)(&Vs[jj][d]) =
                *(const float4*)(qkv + (size_t)(j0 + jj) * (3 * DIM) + (2 * HEADS + h) * DH + d);
        }
        __syncthreads();
        #pragma unroll 4
        for (int jj = 0; jj < 32; jj++) {
            float pr[4];
            #pragma unroll
            for (int r = 0; r < 4; r++) pr[r] = Ps[jj][ty * 4 + r];
            float4 rv = *(const float4*)(&Vs[jj][tx * 4]);
            float vv[4] = {rv.x, rv.y, rv.z, rv.w};
            #pragma unroll
            for (int r = 0; r < 4; r++)
                #pragma unroll
                for (int c = 0; c < 4; c++)
                    acc[r][c] += pr[r] * vv[c];
        }
        __syncthreads();
    }
    #pragma unroll
    for (int r = 0; r < 4; r++) {
        int gi = br * 64 + ty * 4 + r;
        size_t base = (size_t)gi * (3 * DIM);
        #pragma unroll
        for (int c = 0; c < 4; c++) {
            int col = h * DH + tx * 4 + c;
            float v = acc[r][c];
            __nv_bfloat16 hi = __float2bfloat16_rn(v);
            __nv_bfloat16 lo = __float2bfloat16_rn(v - __bfloat162float(hi));
            ab[base + col] = hi;
            ab[base + DIM + col] = lo;
            ab[base + 2 * DIM + col] = hi;
        }
    }
}

// ---------------- launch ----------------
static inline void convw(const float* src, __nv_bfloat16* dst, long long K, long long N) {
    long long KN = K * N;
    convw_kernel<<<(unsigned)((KN + 255) / 256), 256>>>(src, dst, KN);
}

extern "C" void kernel_launch(void* const* d_in, const int* in_sizes, int n_in,
                              void* d_out, int out_size) {
    const int*   tokens      = (const int*)  d_in[0];
    const float* emb         = (const float*)d_in[1];
    const float* gamma_attn  = (const float*)d_in[2];
    const float* w_qkv       = (const float*)d_in[3];
    const float* w_out       = (const float*)d_in[4];
    const float* gamma_ff    = (const float*)d_in[5];
    const float* w_ff1       = (const float*)d_in[6];
    const float* b_ff1       = (const float*)d_in[7];
    const float* w_ff2       = (const float*)d_in[8];
    const float* b_ff2       = (const float*)d_in[9];
    const float* gamma_final = (const float*)d_in[10];
    const float* w_logits    = (const float*)d_in[11];
    float* out = (float*)d_out;

    float *x, *qkv, *sc;
    __nv_bfloat16 *ab, *ab2, *wb;
    cudaGetSymbolAddress((void**)&x,   g_x);
    cudaGetSymbolAddress((void**)&qkv, g_qkv);
    cudaGetSymbolAddress((void**)&sc,  g_sc);
    cudaGetSymbolAddress((void**)&ab,  g_ab);
    cudaGetSymbolAddress((void**)&ab2, g_ab2);
    cudaGetSymbolAddress((void**)&wb,  g_wb);

    // weight conversion (split bf16, K-expanded 3x)
    for (int l = 0; l < DEPTH; l++) {
        convw(w_qkv + (size_t)l * DIM * 3 * DIM, wb + WB_QKV(l), DIM, 3 * DIM);
        convw(w_out + (size_t)l * DIM * DIM,     wb + WB_OUT(l), DIM, DIM);
        convw(w_ff1 + (size_t)l * DIM * FFD,     wb + WB_FF1(l), DIM, FFD);
        convw(w_ff2 + (size_t)l * FFD * DIM,     wb + WB_FF2(l), FFD, DIM);
    }
    convw(w_logits, wb + WB_LOGITS, DIM, VOCAB);

    embed_kernel<<<SEQ * DIM / 256, 256>>>(tokens, emb, x);

    for (int l = 0; l < DEPTH; l++) {
        // --- attention block ---
        rmsnorm_split_kernel<<<SEQ, 256>>>(x, gamma_attn + l * DIM, ab);
        bgemm_kernel<false, false, false, false><<<dim3(3 * DIM / 128, SEQ / 128), 256>>>(
            ab, wb + WB_QKV(l), nullptr, qkv, nullptr, SEQ, 3 * DIM, 3 * DIM);
        rotary_kernel<<<SEQ * 1024 / 256, 256>>>(qkv);
        attn_scores_kernel<<<dim3(SEQ / 64, SEQ / 64, HEADS), 256>>>(qkv, sc);
        softmax_kernel<<<dim3(SEQ, HEADS), 256>>>(sc);
        attn_pv_kernel<<<dim3(SEQ / 64, 1, HEADS), 256>>>(sc, qkv, ab);
        bgemm_kernel<false, true, false, false><<<dim3(DIM / 128, SEQ / 128), 256>>>(
            ab, wb + WB_OUT(l), nullptr, x, nullptr, SEQ, DIM, 3 * DIM);
        // --- feedforward block ---
        rmsnorm_split_kernel<<<SEQ, 256>>>(x, gamma_ff + l * DIM, ab);
        bgemm_kernel<true, false, true, true><<<dim3(FFD / 128, SEQ / 128), 256>>>(
            ab, wb + WB_FF1(l), b_ff1 + (size_t)l * FFD, nullptr, ab2, SEQ, FFD, 3 * DIM);
        bgemm_kernel<true, true, false, false><<<dim3(DIM / 128, SEQ / 128), 256>>>(
            ab2, wb + WB_FF2(l), b_ff2 + (size_t)l * DIM, x, nullptr, SEQ, DIM, 3 * FFD);
    }

    rmsnorm_split_kernel<<<SEQ, 256>>>(x, gamma_final, ab);
    bgemm_kernel<false, false, false, false><<<dim3(VOCAB / 128, SEQ / 128), 256>>>(
        ab, wb + WB_LOGITS, nullptr, out, nullptr, SEQ, VOCAB, 3 * DIM);
}

// round 4
// speedup vs baseline: 1.8502x; 1.0806x over previous
#include <cuda_runtime.h>
#include <cuda_bf16.h>
#include <math.h>
#include <float.h>
#include <stdint.h>

// ---------------- problem constants ----------------
#define SEQ   2048
#define DIM   1024
#define DEPTH 4
#define HEADS 16
#define DH    64
#define FFD   4096
#define VOCAB 32000

// ---------------- scratch (static device globals) ----------------
__device__ float g_x   [SEQ * DIM];                  // residual stream (fp32)
__device__ float g_qkv [SEQ * 3 * DIM];              // qkv projections (fp32)
__device__ __nv_bfloat16 g_ab [SEQ * 3 * DIM];       // split activations (Kp=3072)
__device__ __nv_bfloat16 g_ab2[SEQ * 3 * FFD];       // split activations for ff2 (Kp=12288)
__device__ __nv_bfloat16 g_wb [249298944ull];        // all split weights

// weight offsets in g_wb (bf16 elements)
#define WB_QKV(l)  ((size_t)(l) * 9437184ull)
#define WB_OUT(l)  (37748736ull + (size_t)(l) * 3145728ull)
#define WB_FF1(l)  (50331648ull + (size_t)(l) * 12582912ull)
#define WB_FF2(l)  (100663296ull + (size_t)(l) * 12582912ull)
#define WB_LOGITS  150994944ull

// ---------------- helpers ----------------
__device__ __forceinline__ uint32_t smem_u32(const void* p) {
    return (uint32_t)__cvta_generic_to_shared(p);
}
__device__ __forceinline__ void cp16(uint32_t s, const void* g) {
    asm volatile("cp.async.cg.shared.global [%0], [%1], 16;" :: "r"(s), "l"(g));
}

// ---------------- weight split: w fp32[K,N] -> [Bhi ; Bhi ; Blo] bf16[3K,N] ----
__global__ void __launch_bounds__(256) convw_kernel(const float* __restrict__ w,
                                                    __nv_bfloat16* __restrict__ o,
                                                    long long KN) {
    long long idx = (long long)blockIdx.x * 256 + threadIdx.x;
    if (idx >= KN) return;
    float v = w[idx];
    __nv_bfloat16 hi = __float2bfloat16_rn(v);
    __nv_bfloat16 lo = __float2bfloat16_rn(v - __bfloat162float(hi));
    o[idx] = hi;
    o[idx + KN] = hi;
    o[idx + 2 * KN] = lo;
}

// ---------------- embed ----------------
__global__ void __launch_bounds__(256) embed_kernel(const int* __restrict__ tokens,
                                                    const float* __restrict__ emb,
                                                    float* __restrict__ x) {
    int idx = blockIdx.x * 256 + threadIdx.x;
    int row = idx >> 10;
    int d   = idx & 1023;
    x[idx] = emb[(size_t)tokens[row] * DIM + d];
}

// ---------------- rmsnorm + split: writes A' = [hi | lo | hi] (row stride 3*DIM) ----
__global__ void __launch_bounds__(256) rmsnorm_split_kernel(const float* __restrict__ x,
                                                            const float* __restrict__ gamma,
                                                            __nv_bfloat16* __restrict__ ab) {
    int row = blockIdx.x;
    const float* xr = x + (size_t)row * DIM;
    float ss = 0.f;
    for (int i = threadIdx.x; i < DIM; i += 256) { float v = xr[i]; ss += v * v; }
    __shared__ float red[256];
    red[threadIdx.x] = ss;
    __syncthreads();
    for (int s = 128; s > 0; s >>= 1) {
        if (threadIdx.x < s) red[threadIdx.x] += red[threadIdx.x + s];
        __syncthreads();
    }
    float scale = 32.0f / fmaxf(sqrtf(red[0]), 1e-12f);
    __nv_bfloat16* ar = ab + (size_t)row * (3 * DIM);
    for (int i = threadIdx.x; i < DIM; i += 256) {
        float v = xr[i] * scale * gamma[i];
        __nv_bfloat16 hi = __float2bfloat16_rn(v);
        __nv_bfloat16 lo = __float2bfloat16_rn(v - __bfloat162float(hi));
        ar[i] = hi;
        ar[DIM + i] = lo;
        ar[2 * DIM + i] = hi;
    }
}

// ---------------- rotary on q and k heads (in place in qkv, fp32) ----------------
__global__ void __launch_bounds__(256) rotary_kernel(float* __restrict__ qkv) {
    int idx = blockIdx.x * 256 + threadIdx.x;
    int j    = idx & 31;
    int head = (idx >> 5) & 31;
    int pos  = idx >> 10;
    float inv = powf(10000.0f, -((float)(2 * j)) * (1.0f / 64.0f));
    float f = (float)pos * inv;
    float c = cosf(f), s = sinf(f);
    float* base = qkv + (size_t)pos * (3 * DIM) + head * DH;
    float x1 = base[j], x2 = base[j + 32];
    base[j]      = x1 * c - x2 * s;
    base[j + 32] = x2 * c + x1 * s;
}

// ---------------- bf16 tensor-core GEMM, cp.async double-buffered ----------------
// C[MxN] = A'[Mx(Kp)] @ B'[(Kp)xN]; 128x128x32 tiles, 8 warps, mma m16n8k16 bf16.
#define LDSM4(R0,R1,R2,R3,addr) \
    asm volatile("ldmatrix.sync.aligned.m8n8.x4.shared.b16 {%0,%1,%2,%3},[%4];" \
        : "=r"(R0),"=r"(R1),"=r"(R2),"=r"(R3) : "r"(addr))
#define LDSM4T(R0,R1,R2,R3,addr) \
    asm volatile("ldmatrix.sync.aligned.m8n8.x4.trans.shared.b16 {%0,%1,%2,%3},[%4];" \
        : "=r"(R0),"=r"(R1),"=r"(R2),"=r"(R3) : "r"(addr))
#define MMA16816(d,a,b0,b1) \
    asm volatile("mma.sync.aligned.m16n8k16.row.col.f32.bf16.bf16.f32 " \
        "{%0,%1,%2,%3},{%4,%5,%6,%7},{%8,%9},{%0,%1,%2,%3};" \
        : "+f"(d[0]),"+f"(d[1]),"+f"(d[2]),"+f"(d[3]) \
        : "r"(a[0]),"r"(a[1]),"r"(a[2]),"r"(a[3]),"r"(b0),"r"(b1))

#define AS_STAGE (128 * 40)   // elements
#define BS_STAGE (32 * 136)   // elements

template<bool BIAS, bool RES, bool GELU, bool SPLIT>
__global__ void __launch_bounds__(256)
bgemm_kernel(const __nv_bfloat16* __restrict__ A,
             const __nv_bfloat16* __restrict__ B,
             const float* __restrict__ bias,
             float* __restrict__ C,
             __nv_bfloat16* __restrict__ Cs,
             int M, int N, int Kp)
{
    __shared__ __align__(16) __nv_bfloat16 As[2 * AS_STAGE];
    __shared__ __align__(16) __nv_bfloat16 Bs[2 * BS_STAGE];

    int tid  = threadIdx.x;
    int lane = tid & 31;
    int warp = tid >> 5;
    int wm = warp >> 2;       // 0..1
    int wn = warp & 3;        // 0..3
    int bm = blockIdx.y * 128;
    int bn = blockIdx.x * 128;

    // global load assignments (2 x 16B for A, 2 x 16B for B per thread)
    int ra0 = tid >> 2;            // 0..63
    int ca0 = (tid & 3) * 8;       // 0,8,16,24
    int rb0 = tid >> 4;            // 0..15
    int cb  = (tid & 15) * 8;      // 0..120

    const char* gA0 = (const char*)(A + (size_t)(bm + ra0)      * Kp + ca0);
    const char* gA1 = (const char*)(A + (size_t)(bm + ra0 + 64) * Kp + ca0);
    const char* gB0 = (const char*)(B + (size_t)(rb0)      * N + bn + cb);
    const char* gB1 = (const char*)(B + (size_t)(rb0 + 16) * N + bn + cb);
    size_t bStep = (size_t)64 * N;   // bytes per K-step for B (32 rows)

    uint32_t sAbase = smem_u32(As);
    uint32_t sBbase = smem_u32(Bs);
    uint32_t sA0off = (uint32_t)((ra0 * 40 + ca0) * 2);
    uint32_t sA1off = (uint32_t)(((ra0 + 64) * 40 + ca0) * 2);
    uint32_t sB0off = (uint32_t)((rb0 * 136 + cb) * 2);
    uint32_t sB1off = (uint32_t)(((rb0 + 16) * 136 + cb) * 2);

    // ldmatrix base addresses (per-buffer offset added in loop)
    uint32_t aLd = sAbase + (uint32_t)(((wm * 64 + (lane & 15)) * 40 + (lane >> 4) * 8) * 2);
    uint32_t bLd = sBbase + (uint32_t)(((lane & 15) * 136 + wn * 32 + (lane >> 4) * 8) * 2);

    float acc[4][4][4];
    #pragma unroll
    for (int i = 0; i < 4; i++)
        #pragma unroll
        for (int j = 0; j < 4; j++)
            #pragma unroll
            for (int k = 0; k < 4; k++) acc[i][j][k] = 0.f;

    int steps = Kp >> 5;

    // prologue: stage 0 into buffer 0
    cp16(sAbase + sA0off, gA0);
    cp16(sAbase + sA1off, gA1);
    cp16(sBbase + sB0off, gB0);
    cp16(sBbase + sB1off, gB1);
    asm volatile("cp.async.commit_group;" ::: "memory");

    for (int s = 0; s < steps; s++) {
        int buf = s & 1;
        if (s + 1 < steps) {
            uint32_t oA = (buf ^ 1) * (AS_STAGE * 2);
            uint32_t oB = (buf ^ 1) * (BS_STAGE * 2);
            size_t adv = (size_t)(s + 1) * 64;
            size_t advB = (size_t)(s + 1) * bStep;
            cp16(sAbase + oA + sA0off, gA0 + adv);
            cp16(sAbase + oA + sA1off, gA1 + adv);
            cp16(sBbase + oB + sB0off, gB0 + advB);
            cp16(sBbase + oB + sB1off, gB1 + advB);
            asm volatile("cp.async.commit_group;" ::: "memory");
            asm volatile("cp.async.wait_group 1;" ::: "memory");
        } else {
            asm volatile("cp.async.wait_group 0;" ::: "memory");
        }
        __syncthreads();

        uint32_t aB = aLd + buf * (AS_STAGE * 2);
        uint32_t bB = bLd + buf * (BS_STAGE * 2);
        #pragma unroll
        for (int kk = 0; kk < 2; kk++) {
            uint32_t af[4][4], bf[2][4];
            #pragma unroll
            for (int mt = 0; mt < 4; mt++) {
                uint32_t addr = aB + mt * (16 * 40 * 2) + kk * 32;
                LDSM4(af[mt][0], af[mt][1], af[mt][2], af[mt][3], addr);
            }
            #pragma unroll
            for (int p = 0; p < 2; p++) {
                uint32_t addr = bB + p * 32 + kk * (16 * 136 * 2);
                LDSM4T(bf[p][0], bf[p][1], bf[p][2], bf[p][3], addr);
            }
            #pragma unroll
            for (int mt = 0; mt < 4; mt++) {
                #pragma unroll
                for (int nt = 0; nt < 4; nt++) {
                    uint32_t b0 = bf[nt >> 1][(nt & 1) * 2];
                    uint32_t b1 = bf[nt >> 1][(nt & 1) * 2 + 1];
                    MMA16816(acc[mt][nt], af[mt], b0, b1);
                }
            }
        }
        __syncthreads();
    }

    // epilogue
    int row0 = bm + wm * 64;
    int col0 = bn + wn * 32;
    #pragma unroll
    for (int mt = 0; mt < 4; mt++) {
        #pragma unroll
        for (int nt = 0; nt < 4; nt++) {
            int r = row0 + mt * 16 + (lane >> 2);
            int c = col0 + nt * 8 + (lane & 3) * 2;
            #pragma unroll
            for (int half = 0; half < 2; half++) {
                int rr = r + half * 8;
                #pragma unroll
                for (int e = 0; e < 2; e++) {
                    float val = acc[mt][nt][half * 2 + e];
                    int cc = c + e;
                    if (BIAS) val += bias[cc];
                    if (GELU) val = 0.5f * val * (1.0f + erff(val * 0.70710678118654752f));
                    if (SPLIT) {
                        __nv_bfloat16 hi = __float2bfloat16_rn(val);
                        __nv_bfloat16 lo = __float2bfloat16_rn(val - __bfloat162float(hi));
                        size_t base = (size_t)rr * (3 * (size_t)N);
                        Cs[base + cc] = hi;
                        Cs[base + N + cc] = lo;
                        Cs[base + 2 * (size_t)N + cc] = hi;
                    } else {
                        size_t off = (size_t)rr * N + cc;
                        if (RES) val += C[off];
                        C[off] = val;
                    }
                }
            }
        }
    }
}

// ---------------- fused flash attention (fp32, causal) ----------------
// grid (SEQ/64, HEADS), 256 threads. Q block 64 rows; streams 64-row K/V tiles.
// Writes O directly in split-bf16 A'-format (row stride 3*DIM) for the out-proj.
__global__ void __launch_bounds__(256) flash_kernel(const float* __restrict__ qkv,
                                                    __nv_bfloat16* __restrict__ ab) {
    extern __shared__ float fsm[];
    float* Qs = fsm;                   // [64][64]  (d-major: Qs[d][i])
    float* Ks = Qs + 64 * 64;          // [64][64]  (d-major: Ks[d][j])
    float* Vs = Ks + 64 * 64;          // [64][68]  (Vs[j][d], padded)
    float* Ps = Vs + 64 * 68;          // [64][65]  (Ps[j][i], padded)

    int br = gridDim.x - 1 - blockIdx.x;   // heavy blocks first
    int h  = blockIdx.y;
    int tid = threadIdx.x;
    int tx = tid & 15, ty = tid >> 4;

    // load Q tile (pre-scaled by DH^-0.5), transposed to [d][i]
    const float* qb = qkv + (size_t)br * 64 * (3 * DIM) + h * DH;
    #pragma unroll
    for (int l = 0; l < 4; l++) {
        int i = tid + l * 256;
        int r  = i >> 4;
        int d4 = (i & 15) * 4;
        float4 v = *(const float4*)(qb + (size_t)r * (3 * DIM) + d4);
        Qs[(d4 + 0) * 64 + r] = v.x * 0.125f;
        Qs[(d4 + 1) * 64 + r] = v.y * 0.125f;
        Qs[(d4 + 2) * 64 + r] = v.z * 0.125f;
        Qs[(d4 + 3) * 64 + r] = v.w * 0.125f;
    }

    float run_max[4], run_sum[4], O[4][4];
    #pragma unroll
    for (int r = 0; r < 4; r++) {
        run_max[r] = -FLT_MAX; run_sum[r] = 0.f;
        #pragma unroll
        for (int c = 0; c < 4; c++) O[r][c] = 0.f;
    }

    for (int kb = 0; kb <= br; kb++) {
        __syncthreads();   // previous PV done reading Vs/Ps; Q load done (first iter)
        const float* kbp = qkv + (size_t)kb * 64 * (3 * DIM) + (HEADS + h) * DH;
        const float* vbp = qkv + (size_t)kb * 64 * (3 * DIM) + (2 * HEADS + h) * DH;
        #pragma unroll
        for (int l = 0; l < 4; l++) {
            int i = tid + l * 256;
            int r  = i >> 4;
            int d4 = (i & 15) * 4;
            float4 w = *(const float4*)(kbp + (size_t)r * (3 * DIM) + d4);
            Ks[(d4 + 0) * 64 + r] = w.x; Ks[(d4 + 1) * 64 + r] = w.y;
            Ks[(d4 + 2) * 64 + r] = w.z; Ks[(d4 + 3) * 64 + r] = w.w;
            float4 u = *(const float4*)(vbp + (size_t)r * (3 * DIM) + d4);
            *(float4*)(Vs + r * 68 + d4) = u;
        }
        __syncthreads();

        // S = Q K^T (4x4 per thread)
        float acc[4][4];
        #pragma unroll
        for (int r = 0; r < 4; r++)
            #pragma unroll
            for (int c = 0; c < 4; c++) acc[r][c] = 0.f;
        #pragma unroll 4
        for (int d = 0; d < 64; d++) {
            float4 rq = *(const float4*)(Qs + d * 64 + ty * 4);
            float4 rk = *(const float4*)(Ks + d * 64 + tx * 4);
            float qa[4] = {rq.x, rq.y, rq.z, rq.w};
            float ka[4] = {rk.x, rk.y, rk.z, rk.w};
            #pragma unroll
            for (int r = 0; r < 4; r++)
                #pragma unroll
                for (int c = 0; c < 4; c++)
                    acc[r][c] += qa[r] * ka[c];
        }

        // causal mask on diagonal tile
        if (kb == br) {
            #pragma unroll
            for (int r = 0; r < 4; r++) {
                int gi = ty * 4 + r;
                #pragma unroll
                for (int c = 0; c < 4; c++) {
                    int gj = tx * 4 + c;
                    if (gj > gi) acc[r][c] = -FLT_MAX;
                }
            }
        }

        // online softmax update per row
        float alpha[4];
        #pragma unroll
        for (int r = 0; r < 4; r++) {
            float mt = fmaxf(fmaxf(acc[r][0], acc[r][1]), fmaxf(acc[r][2], acc[r][3]));
            #pragma unroll
            for (int msk = 8; msk > 0; msk >>= 1)
                mt = fmaxf(mt, __shfl_xor_sync(0xffffffffu, mt, msk));
            float nm = fmaxf(run_max[r], mt);
            alpha[r] = expf(run_max[r] - nm);
            run_max[r] = nm;
            float ps = 0.f;
            #pragma unroll
            for (int c = 0; c < 4; c++) {
                float p = expf(acc[r][c] - nm);
                acc[r][c] = p;
                ps += p;
            }
            #pragma unroll
            for (int msk = 8; msk > 0; msk >>= 1)
                ps += __shfl_xor_sync(0xffffffffu, ps, msk);
            run_sum[r] = run_sum[r] * alpha[r] + ps;
        }

        // stash P transposed: Ps[j][i]
        #pragma unroll
        for (int r = 0; r < 4; r++)
            #pragma unroll
            for (int c = 0; c < 4; c++)
                Ps[(tx * 4 + c) * 65 + ty * 4 + r] = acc[r][c];
        __syncthreads();

        // O = alpha*O + P V
        #pragma unroll
        for (int r = 0; r < 4; r++)
            #pragma unroll
            for (int c = 0; c < 4; c++) O[r][c] *= alpha[r];
        #pragma unroll 4
        for (int jj = 0; jj < 64; jj++) {
            float pr[4];
            #pragma unroll
            for (int r = 0; r < 4; r++) pr[r] = Ps[jj * 65 + ty * 4 + r];
            float4 rv = *(const float4*)(Vs + jj * 68 + tx * 4);
            float vv[4] = {rv.x, rv.y, rv.z, rv.w};
            #pragma unroll
            for (int r = 0; r < 4; r++)
                #pragma unroll
                for (int c = 0; c < 4; c++)
                    O[r][c] += pr[r] * vv[c];
        }
    }

    // normalize + write split-bf16 rows
    #pragma unroll
    for (int r = 0; r < 4; r++) {
        int gi = br * 64 + ty * 4 + r;
        float inv = 1.0f / run_sum[r];
        size_t base = (size_t)gi * (3 * DIM);
        #pragma unroll
        for (int c = 0; c < 4; c++) {
            int col = h * DH + tx * 4 + c;
            float v = O[r][c] * inv;
            __nv_bfloat16 hi = __float2bfloat16_rn(v);
            __nv_bfloat16 lo = __float2bfloat16_rn(v - __bfloat162float(hi));
            ab[base + col] = hi;
            ab[base + DIM + col] = lo;
            ab[base + 2 * DIM + col] = hi;
        }
    }
}

#define FLASH_SMEM ((64 * 64 + 64 * 64 + 64 * 68 + 64 * 65) * 4)

// ---------------- launch ----------------
static inline void convw(const float* src, __nv_bfloat16* dst, long long K, long long N) {
    long long KN = K * N;
    convw_kernel<<<(unsigned)((KN + 255) / 256), 256>>>(src, dst, KN);
}

extern "C" void kernel_launch(void* const* d_in, const int* in_sizes, int n_in,
                              void* d_out, int out_size) {
    const int*   tokens      = (const int*)  d_in[0];
    const float* emb         = (const float*)d_in[1];
    const float* gamma_attn  = (const float*)d_in[2];
    const float* w_qkv       = (const float*)d_in[3];
    const float* w_out       = (const float*)d_in[4];
    const float* gamma_ff    = (const float*)d_in[5];
    const float* w_ff1       = (const float*)d_in[6];
    const float* b_ff1       = (const float*)d_in[7];
    const float* w_ff2       = (const float*)d_in[8];
    const float* b_ff2       = (const float*)d_in[9];
    const float* gamma_final = (const float*)d_in[10];
    const float* w_logits    = (const float*)d_in[11];
    float* out = (float*)d_out;

    float *x, *qkv;
    __nv_bfloat16 *ab, *ab2, *wb;
    cudaGetSymbolAddress((void**)&x,   g_x);
    cudaGetSymbolAddress((void**)&qkv, g_qkv);
    cudaGetSymbolAddress((void**)&ab,  g_ab);
    cudaGetSymbolAddress((void**)&ab2, g_ab2);
    cudaGetSymbolAddress((void**)&wb,  g_wb);

    cudaFuncSetAttribute(flash_kernel, cudaFuncAttributeMaxDynamicSharedMemorySize,
                         FLASH_SMEM);

    // weight conversion (split bf16, K-expanded 3x)
    for (int l = 0; l < DEPTH; l++) {
        convw(w_qkv + (size_t)l * DIM * 3 * DIM, wb + WB_QKV(l), DIM, 3 * DIM);
        convw(w_out + (size_t)l * DIM * DIM,     wb + WB_OUT(l), DIM, DIM);
        convw(w_ff1 + (size_t)l * DIM * FFD,     wb + WB_FF1(l), DIM, FFD);
        convw(w_ff2 + (size_t)l * FFD * DIM,     wb + WB_FF2(l), FFD, DIM);
    }
    convw(w_logits, wb + WB_LOGITS, DIM, VOCAB);

    embed_kernel<<<SEQ * DIM / 256, 256>>>(tokens, emb, x);

    for (int l = 0; l < DEPTH; l++) {
        // --- attention block ---
        rmsnorm_split_kernel<<<SEQ, 256>>>(x, gamma_attn + l * DIM, ab);
        bgemm_kernel<false, false, false, false><<<dim3(3 * DIM / 128, SEQ / 128), 256>>>(
            ab, wb + WB_QKV(l), nullptr, qkv, nullptr, SEQ, 3 * DIM, 3 * DIM);
        rotary_kernel<<<SEQ * 1024 / 256, 256>>>(qkv);
        flash_kernel<<<dim3(SEQ / 64, HEADS), 256, FLASH_SMEM>>>(qkv, ab);
        bgemm_kernel<false, true, false, false><<<dim3(DIM / 128, SEQ / 128), 256>>>(
            ab, wb + WB_OUT(l), nullptr, x, nullptr, SEQ, DIM, 3 * DIM);
        // --- feedforward block ---
        rmsnorm_split_kernel<<<SEQ, 256>>>(x, gamma_ff + l * DIM, ab);
        bgemm_kernel<true, false, true, true><<<dim3(FFD / 128, SEQ / 128), 256>>>(
            ab, wb + WB_FF1(l), b_ff1 + (size_t)l * FFD, nullptr, ab2, SEQ, FFD, 3 * DIM);
        bgemm_kernel<true, true, false, false><<<dim3(DIM / 128, SEQ / 128), 256>>>(
            ab2, wb + WB_FF2(l), b_ff2 + (size_t)l * DIM, x, nullptr, SEQ, DIM, 3 * FFD);
    }

    rmsnorm_split_kernel<<<SEQ, 256>>>(x, gamma_final, ab);
    bgemm_kernel<false, false, false, false><<<dim3(VOCAB / 128, SEQ / 128), 256>>>(
        ab, wb + WB_LOGITS, nullptr, out, nullptr, SEQ, VOCAB, 3 * DIM);
}

// round 5
// speedup vs baseline: 1.9147x; 1.0349x over previous
#include <cuda_runtime.h>
#include <cuda_bf16.h>
#include <math.h>
#include <float.h>
#include <stdint.h>

// ---------------- problem constants ----------------
#define SEQ   2048
#define DIM   1024
#define DEPTH 4
#define HEADS 16
#define DH    64
#define FFD   4096
#define VOCAB 32000

// ---------------- scratch (static device globals) ----------------
__device__ float g_x   [SEQ * DIM];                  // residual stream (fp32)
__device__ float g_qkv [SEQ * 3 * DIM];              // qkv projections (fp32)
__device__ __nv_bfloat16 g_ab [SEQ * 3 * DIM];       // split activations (Kp=3072)
__device__ __nv_bfloat16 g_ab2[SEQ * 3 * FFD];       // split activations for ff2 (Kp=12288)
__device__ __nv_bfloat16 g_wb [249298944ull];        // all split weights

// weight offsets in g_wb (bf16 elements)
#define WB_QKV(l)  ((size_t)(l) * 9437184ull)
#define WB_OUT(l)  (37748736ull + (size_t)(l) * 3145728ull)
#define WB_FF1(l)  (50331648ull + (size_t)(l) * 12582912ull)
#define WB_FF2(l)  (100663296ull + (size_t)(l) * 12582912ull)
#define WB_LOGITS  150994944ull

// ---------------- helpers ----------------
__device__ __forceinline__ uint32_t smem_u32(const void* p) {
    return (uint32_t)__cvta_generic_to_shared(p);
}
__device__ __forceinline__ void cp16(uint32_t s, const void* g) {
    asm volatile("cp.async.cg.shared.global [%0], [%1], 16;" :: "r"(s), "l"(g));
}

// ---------------- weight split (vectorized): fp32[K,N] -> [Bhi;Bhi;Blo] bf16[3K,N] ----
__global__ void __launch_bounds__(256) convw_kernel(const float4* __restrict__ w,
                                                    __nv_bfloat16* __restrict__ o,
                                                    long long KN4) {
    long long idx = (long long)blockIdx.x * 256 + threadIdx.x;
    if (idx >= KN4) return;
    float4 v = w[idx];
    union { unsigned short u[4]; uint2 p; } hi4, lo4;
    float vv[4] = {v.x, v.y, v.z, v.w};
    #pragma unroll
    for (int e = 0; e < 4; e++) {
        __nv_bfloat16 hi = __float2bfloat16_rn(vv[e]);
        __nv_bfloat16 lo = __float2bfloat16_rn(vv[e] - __bfloat162float(hi));
        hi4.u[e] = *(unsigned short*)&hi;
        lo4.u[e] = *(unsigned short*)&lo;
    }
    long long KN = KN4 * 4;
    *(uint2*)(o + 4 * idx)          = hi4.p;
    *(uint2*)(o + KN + 4 * idx)     = hi4.p;
    *(uint2*)(o + 2 * KN + 4 * idx) = lo4.p;
}

// ---------------- embed ----------------
__global__ void __launch_bounds__(256) embed_kernel(const int* __restrict__ tokens,
                                                    const float* __restrict__ emb,
                                                    float* __restrict__ x) {
    int idx = blockIdx.x * 256 + threadIdx.x;
    int row = idx >> 10;
    int d   = idx & 1023;
    x[idx] = emb[(size_t)tokens[row] * DIM + d];
}

// ---------------- rmsnorm + split: writes A' = [hi | lo | hi] (row stride 3*DIM) ----
__global__ void __launch_bounds__(256) rmsnorm_split_kernel(const float* __restrict__ x,
                                                            const float* __restrict__ gamma,
                                                            __nv_bfloat16* __restrict__ ab) {
    int row = blockIdx.x;
    const float* xr = x + (size_t)row * DIM;
    float ss = 0.f;
    for (int i = threadIdx.x; i < DIM; i += 256) { float v = xr[i]; ss += v * v; }
    __shared__ float red[256];
    red[threadIdx.x] = ss;
    __syncthreads();
    for (int s = 128; s > 0; s >>= 1) {
        if (threadIdx.x < s) red[threadIdx.x] += red[threadIdx.x + s];
        __syncthreads();
    }
    float scale = 32.0f / fmaxf(sqrtf(red[0]), 1e-12f);
    __nv_bfloat16* ar = ab + (size_t)row * (3 * DIM);
    for (int i = threadIdx.x; i < DIM; i += 256) {
        float v = xr[i] * scale * gamma[i];
        __nv_bfloat16 hi = __float2bfloat16_rn(v);
        __nv_bfloat16 lo = __float2bfloat16_rn(v - __bfloat162float(hi));
        ar[i] = hi;
        ar[DIM + i] = lo;
        ar[2 * DIM + i] = hi;
    }
}

// ---------------- rotary on q and k heads (in place in qkv, fp32) ----------------
__global__ void __launch_bounds__(256) rotary_kernel(float* __restrict__ qkv) {
    int idx = blockIdx.x * 256 + threadIdx.x;
    int j    = idx & 31;
    int head = (idx >> 5) & 31;
    int pos  = idx >> 10;
    float inv = powf(10000.0f, -((float)(2 * j)) * (1.0f / 64.0f));
    float f = (float)pos * inv;
    float c = cosf(f), s = sinf(f);
    float* base = qkv + (size_t)pos * (3 * DIM) + head * DH;
    float x1 = base[j], x2 = base[j + 32];
    base[j]      = x1 * c - x2 * s;
    base[j + 32] = x2 * c + x1 * s;
}

// ---------------- bf16 tensor-core GEMM, 5-stage cp.async pipeline ----------------
// C[MxN] = A'[Mx(Kp)] @ B'[(Kp)xN]; 128x128x32 tiles, 8 warps, mma m16n8k16 bf16.
#define LDSM4(R0,R1,R2,R3,addr) \
    asm volatile("ldmatrix.sync.aligned.m8n8.x4.shared.b16 {%0,%1,%2,%3},[%4];" \
        : "=r"(R0),"=r"(R1),"=r"(R2),"=r"(R3) : "r"(addr))
#define LDSM4T(R0,R1,R2,R3,addr) \
    asm volatile("ldmatrix.sync.aligned.m8n8.x4.trans.shared.b16 {%0,%1,%2,%3},[%4];" \
        : "=r"(R0),"=r"(R1),"=r"(R2),"=r"(R3) : "r"(addr))
#define MMA16816(d,a,b0,b1) \
    asm volatile("mma.sync.aligned.m16n8k16.row.col.f32.bf16.bf16.f32 " \
        "{%0,%1,%2,%3},{%4,%5,%6,%7},{%8,%9},{%0,%1,%2,%3};" \
        : "+f"(d[0]),"+f"(d[1]),"+f"(d[2]),"+f"(d[3]) \
        : "r"(a[0]),"r"(a[1]),"r"(a[2]),"r"(a[3]),"r"(b0),"r"(b1))

#define NSTAGE 5
#define A_STG_B 10240                 // 128 rows * 40 stride * 2B
#define B_STG_B 8704                  // 32 rows * 136 stride * 2B
#define SSTG_B  (A_STG_B + B_STG_B)   // 18944 bytes per stage
#define GEMM_SMEM (NSTAGE * SSTG_B)   // 94720 bytes

template<bool BIAS, bool RES, bool GELU, bool SPLIT>
__global__ void __launch_bounds__(256)
bgemm_kernel(const __nv_bfloat16* __restrict__ A,
             const __nv_bfloat16* __restrict__ B,
             const float* __restrict__ bias,
             float* __restrict__ C,
             __nv_bfloat16* __restrict__ Cs,
             int M, int N, int Kp)
{
    extern __shared__ __align__(16) __nv_bfloat16 sm[];
    uint32_t sbase = smem_u32(sm);

    int tid  = threadIdx.x;
    int lane = tid & 31;
    int warp = tid >> 5;
    int wm = warp >> 2;       // 0..1
    int wn = warp & 3;        // 0..3
    int bm = blockIdx.y * 128;
    int bn = blockIdx.x * 128;

    // global load assignments (2 x 16B for A, 2 x 16B for B per thread)
    int ra0 = tid >> 2;            // 0..63
    int ca0 = (tid & 3) * 8;       // 0,8,16,24
    int rb0 = tid >> 4;            // 0..15
    int cb  = (tid & 15) * 8;      // 0..120

    const char* gA0 = (const char*)(A + (size_t)(bm + ra0)      * Kp + ca0);
    const char* gA1 = (const char*)(A + (size_t)(bm + ra0 + 64) * Kp + ca0);
    const char* gB0 = (const char*)(B + (size_t)(rb0)      * N + bn + cb);
    const char* gB1 = (const char*)(B + (size_t)(rb0 + 16) * N + bn + cb);
    size_t bStep = (size_t)64 * N;   // bytes per K-step for B (32 rows)

    uint32_t sA0off = (uint32_t)((ra0 * 40 + ca0) * 2);
    uint32_t sA1off = (uint32_t)(((ra0 + 64) * 40 + ca0) * 2);
    uint32_t sB0off = (uint32_t)(A_STG_B + (rb0 * 136 + cb) * 2);
    uint32_t sB1off = (uint32_t)(A_STG_B + ((rb0 + 16) * 136 + cb) * 2);

    // ldmatrix fragment offsets (relative to stage base)
    uint32_t aFrag = (uint32_t)(((wm * 64 + (lane & 15)) * 40 + (lane >> 4) * 8) * 2);
    uint32_t bFrag = (uint32_t)(A_STG_B + ((lane & 15) * 136 + wn * 32 + (lane >> 4) * 8) * 2);

    float acc[4][4][4];
    #pragma unroll
    for (int i = 0; i < 4; i++)
        #pragma unroll
        for (int j = 0; j < 4; j++)
            #pragma unroll
            for (int k = 0; k < 4; k++) acc[i][j][k] = 0.f;

    int steps = Kp >> 5;

    auto load_stage = [&](int t) {
        uint32_t so = sbase + (uint32_t)(t % NSTAGE) * SSTG_B;
        size_t advA = (size_t)t * 64;
        size_t advB = (size_t)t * bStep;
        cp16(so + sA0off, gA0 + advA);
        cp16(so + sA1off, gA1 + advA);
        cp16(so + sB0off, gB0 + advB);
        cp16(so + sB1off, gB1 + advB);
        asm volatile("cp.async.commit_group;" ::: "memory");
    };

    // prologue: stages 0..3
    #pragma unroll
    for (int t = 0; t < NSTAGE - 1; t++) load_stage(t);

    for (int s = 0; s < steps; s++) {
        int rem = steps - 1 - s;
        if (rem >= 3)      asm volatile("cp.async.wait_group 3;" ::: "memory");
        else if (rem == 2) asm volatile("cp.async.wait_group 2;" ::: "memory");
        else if (rem == 1) asm volatile("cp.async.wait_group 1;" ::: "memory");
        else               asm volatile("cp.async.wait_group 0;" ::: "memory");
        __syncthreads();

        if (s + NSTAGE - 1 < steps) load_stage(s + NSTAGE - 1);

        uint32_t stg = sbase + (uint32_t)(s % NSTAGE) * SSTG_B;
        uint32_t aB = stg + aFrag;
        uint32_t bB = stg + bFrag;
        #pragma unroll
        for (int kk = 0; kk < 2; kk++) {
            uint32_t af[4][4], bf[2][4];
            #pragma unroll
            for (int mt = 0; mt < 4; mt++) {
                uint32_t addr = aB + mt * (16 * 40 * 2) + kk * 32;
                LDSM4(af[mt][0], af[mt][1], af[mt][2], af[mt][3], addr);
            }
            #pragma unroll
            for (int p = 0; p < 2; p++) {
                uint32_t addr = bB + p * 32 + kk * (16 * 136 * 2);
                LDSM4T(bf[p][0], bf[p][1], bf[p][2], bf[p][3], addr);
            }
            #pragma unroll
            for (int mt = 0; mt < 4; mt++) {
                #pragma unroll
                for (int nt = 0; nt < 4; nt++) {
                    uint32_t b0 = bf[nt >> 1][(nt & 1) * 2];
                    uint32_t b1 = bf[nt >> 1][(nt & 1) * 2 + 1];
                    MMA16816(acc[mt][nt], af[mt], b0, b1);
                }
            }
        }
    }

    // epilogue
    int row0 = bm + wm * 64;
    int col0 = bn + wn * 32;
    #pragma unroll
    for (int mt = 0; mt < 4; mt++) {
        #pragma unroll
        for (int nt = 0; nt < 4; nt++) {
            int r = row0 + mt * 16 + (lane >> 2);
            int c = col0 + nt * 8 + (lane & 3) * 2;
            #pragma unroll
            for (int half = 0; half < 2; half++) {
                int rr = r + half * 8;
                #pragma unroll
                for (int e = 0; e < 2; e++) {
                    float val = acc[mt][nt][half * 2 + e];
                    int cc = c + e;
                    if (BIAS) val += bias[cc];
                    if (GELU) val = 0.5f * val * (1.0f + erff(val * 0.70710678118654752f));
                    if (SPLIT) {
                        __nv_bfloat16 hi = __float2bfloat16_rn(val);
                        __nv_bfloat16 lo = __float2bfloat16_rn(val - __bfloat162float(hi));
                        size_t base = (size_t)rr * (3 * (size_t)N);
                        Cs[base + cc] = hi;
                        Cs[base + N + cc] = lo;
                        Cs[base + 2 * (size_t)N + cc] = hi;
                    } else {
                        size_t off = (size_t)rr * N + cc;
                        if (RES) val += C[off];
                        C[off] = val;
                    }
                }
            }
        }
    }
}

// ---------------- fused flash attention (fp32, causal) ----------------
__global__ void __launch_bounds__(256) flash_kernel(const float* __restrict__ qkv,
                                                    __nv_bfloat16* __restrict__ ab) {
    extern __shared__ float fsm[];
    float* Qs = fsm;                   // [64][64]  (d-major)
    float* Ks = Qs + 64 * 64;          // [64][64]  (d-major)
    float* Vs = Ks + 64 * 64;          // [64][68]
    float* Ps = Vs + 64 * 68;          // [64][65]

    int br = gridDim.x - 1 - blockIdx.x;
    int h  = blockIdx.y;
    int tid = threadIdx.x;
    int tx = tid & 15, ty = tid >> 4;

    const float* qb = qkv + (size_t)br * 64 * (3 * DIM) + h * DH;
    #pragma unroll
    for (int l = 0; l < 4; l++) {
        int i = tid + l * 256;
        int r  = i >> 4;
        int d4 = (i & 15) * 4;
        float4 v = *(const float4*)(qb + (size_t)r * (3 * DIM) + d4);
        Qs[(d4 + 0) * 64 + r] = v.x * 0.125f;
        Qs[(d4 + 1) * 64 + r] = v.y * 0.125f;
        Qs[(d4 + 2) * 64 + r] = v.z * 0.125f;
        Qs[(d4 + 3) * 64 + r] = v.w * 0.125f;
    }

    float run_max[4], run_sum[4], O[4][4];
    #pragma unroll
    for (int r = 0; r < 4; r++) {
        run_max[r] = -FLT_MAX; run_sum[r] = 0.f;
        #pragma unroll
        for (int c = 0; c < 4; c++) O[r][c] = 0.f;
    }

    for (int kb = 0; kb <= br; kb++) {
        __syncthreads();
        const float* kbp = qkv + (size_t)kb * 64 * (3 * DIM) + (HEADS + h) * DH;
        const float* vbp = qkv + (size_t)kb * 64 * (3 * DIM) + (2 * HEADS + h) * DH;
        #pragma unroll
        for (int l = 0; l < 4; l++) {
            int i = tid + l * 256;
            int r  = i >> 4;
            int d4 = (i & 15) * 4;
            float4 w = *(const float4*)(kbp + (size_t)r * (3 * DIM) + d4);
            Ks[(d4 + 0) * 64 + r] = w.x; Ks[(d4 + 1) * 64 + r] = w.y;
            Ks[(d4 + 2) * 64 + r] = w.z; Ks[(d4 + 3) * 64 + r] = w.w;
            float4 u = *(const float4*)(vbp + (size_t)r * (3 * DIM) + d4);
            *(float4*)(Vs + r * 68 + d4) = u;
        }
        __syncthreads();

        float acc[4][4];
        #pragma unroll
        for (int r = 0; r < 4; r++)
            #pragma unroll
            for (int c = 0; c < 4; c++) acc[r][c] = 0.f;
        #pragma unroll 4
        for (int d = 0; d < 64; d++) {
            float4 rq = *(const float4*)(Qs + d * 64 + ty * 4);
            float4 rk = *(const float4*)(Ks + d * 64 + tx * 4);
            float qa[4] = {rq.x, rq.y, rq.z, rq.w};
            float ka[4] = {rk.x, rk.y, rk.z, rk.w};
            #pragma unroll
            for (int r = 0; r < 4; r++)
                #pragma unroll
                for (int c = 0; c < 4; c++)
                    acc[r][c] += qa[r] * ka[c];
        }

        if (kb == br) {
            #pragma unroll
            for (int r = 0; r < 4; r++) {
                int gi = ty * 4 + r;
                #pragma unroll
                for (int c = 0; c < 4; c++) {
                    int gj = tx * 4 + c;
                    if (gj > gi) acc[r][c] = -FLT_MAX;
                }
            }
        }

        float alpha[4];
        #pragma unroll
        for (int r = 0; r < 4; r++) {
            float mt = fmaxf(fmaxf(acc[r][0], acc[r][1]), fmaxf(acc[r][2], acc[r][3]));
            #pragma unroll
            for (int msk = 8; msk > 0; msk >>= 1)
                mt = fmaxf(mt, __shfl_xor_sync(0xffffffffu, mt, msk));
            float nm = fmaxf(run_max[r], mt);
            alpha[r] = expf(run_max[r] - nm);
            run_max[r] = nm;
            float ps = 0.f;
            #pragma unroll
            for (int c = 0; c < 4; c++) {
                float p = expf(acc[r][c] - nm);
                acc[r][c] = p;
                ps += p;
            }
            #pragma unroll
            for (int msk = 8; msk > 0; msk >>= 1)
                ps += __shfl_xor_sync(0xffffffffu, ps, msk);
            run_sum[r] = run_sum[r] * alpha[r] + ps;
        }

        #pragma unroll
        for (int r = 0; r < 4; r++)
            #pragma unroll
            for (int c = 0; c < 4; c++)
                Ps[(tx * 4 + c) * 65 + ty * 4 + r] = acc[r][c];
        __syncthreads();

        #pragma unroll
        for (int r = 0; r < 4; r++)
            #pragma unroll
            for (int c = 0; c < 4; c++) O[r][c] *= alpha[r];
        #pragma unroll 4
        for (int jj = 0; jj < 64; jj++) {
            float pr[4];
            #pragma unroll
            for (int r = 0; r < 4; r++) pr[r] = Ps[jj * 65 + ty * 4 + r];
            float4 rv = *(const float4*)(Vs + jj * 68 + tx * 4);
            float vv[4] = {rv.x, rv.y, rv.z, rv.w};
            #pragma unroll
            for (int r = 0; r < 4; r++)
                #pragma unroll
                for (int c = 0; c < 4; c++)
                    O[r][c] += pr[r] * vv[c];
        }
    }

    #pragma unroll
    for (int r = 0; r < 4; r++) {
        int gi = br * 64 + ty * 4 + r;
        float inv = 1.0f / run_sum[r];
        size_t base = (size_t)gi * (3 * DIM);
        #pragma unroll
        for (int c = 0; c < 4; c++) {
            int col = h * DH + tx * 4 + c;
            float v = O[r][c] * inv;
            __nv_bfloat16 hi = __float2bfloat16_rn(v);
            __nv_bfloat16 lo = __float2bfloat16_rn(v - __bfloat162float(hi));
            ab[base + col] = hi;
            ab[base + DIM + col] = lo;
            ab[base + 2 * DIM + col] = hi;
        }
    }
}

#define FLASH_SMEM ((64 * 64 + 64 * 64 + 64 * 68 + 64 * 65) * 4)

// ---------------- launch ----------------
static inline void convw(const float* src, __nv_bfloat16* dst, long long K, long long N) {
    long long KN4 = K * N / 4;
    convw_kernel<<<(unsigned)((KN4 + 255) / 256), 256>>>((const float4*)src, dst, KN4);
}

extern "C" void kernel_launch(void* const* d_in, const int* in_sizes, int n_in,
                              void* d_out, int out_size) {
    const int*   tokens      = (const int*)  d_in[0];
    const float* emb         = (const float*)d_in[1];
    const float* gamma_attn  = (const float*)d_in[2];
    const float* w_qkv       = (const float*)d_in[3];
    const float* w_out       = (const float*)d_in[4];
    const float* gamma_ff    = (const float*)d_in[5];
    const float* w_ff1       = (const float*)d_in[6];
    const float* b_ff1       = (const float*)d_in[7];
    const float* w_ff2       = (const float*)d_in[8];
    const float* b_ff2       = (const float*)d_in[9];
    const float* gamma_final = (const float*)d_in[10];
    const float* w_logits    = (const float*)d_in[11];
    float* out = (float*)d_out;

    float *x, *qkv;
    __nv_bfloat16 *ab, *ab2, *wb;
    cudaGetSymbolAddress((void**)&x,   g_x);
    cudaGetSymbolAddress((void**)&qkv, g_qkv);
    cudaGetSymbolAddress((void**)&ab,  g_ab);
    cudaGetSymbolAddress((void**)&ab2, g_ab2);
    cudaGetSymbolAddress((void**)&wb,  g_wb);

    cudaFuncSetAttribute(flash_kernel, cudaFuncAttributeMaxDynamicSharedMemorySize,
                         FLASH_SMEM);
    cudaFuncSetAttribute(bgemm_kernel<false, false, false, false>,
                         cudaFuncAttributeMaxDynamicSharedMemorySize, GEMM_SMEM);
    cudaFuncSetAttribute(bgemm_kernel<false, true, false, false>,
                         cudaFuncAttributeMaxDynamicSharedMemorySize, GEMM_SMEM);
    cudaFuncSetAttribute(bgemm_kernel<true, false, true, true>,
                         cudaFuncAttributeMaxDynamicSharedMemorySize, GEMM_SMEM);
    cudaFuncSetAttribute(bgemm_kernel<true, true, false, false>,
                         cudaFuncAttributeMaxDynamicSharedMemorySize, GEMM_SMEM);

    // launch order arranged so launch index 5 is the first (qkv) bgemm for ncu -s 5
    embed_kernel<<<SEQ * DIM / 256, 256>>>(tokens, emb, x);                       // 0

    for (int l = 0; l < DEPTH; l++) {
        convw(w_qkv + (size_t)l * DIM * 3 * DIM, wb + WB_QKV(l), DIM, 3 * DIM);   // 1
        convw(w_out + (size_t)l * DIM * DIM,     wb + WB_OUT(l), DIM, DIM);       // 2
        convw(w_ff1 + (size_t)l * DIM * FFD,     wb + WB_FF1(l), DIM, FFD);       // 3
        // --- attention block ---
        rmsnorm_split_kernel<<<SEQ, 256>>>(x, gamma_attn + l * DIM, ab);          // 4
        bgemm_kernel<false, false, false, false><<<dim3(3 * DIM / 128, SEQ / 128), 256, GEMM_SMEM>>>(
            ab, wb + WB_QKV(l), nullptr, qkv, nullptr, SEQ, 3 * DIM, 3 * DIM);    // 5  <- profiled
        rotary_kernel<<<SEQ * 1024 / 256, 256>>>(qkv);
        flash_kernel<<<dim3(SEQ / 64, HEADS), 256, FLASH_SMEM>>>(qkv, ab);
        bgemm_kernel<false, true, false, false><<<dim3(DIM / 128, SEQ / 128), 256, GEMM_SMEM>>>(
            ab, wb + WB_OUT(l), nullptr, x, nullptr, SEQ, DIM, 3 * DIM);
        // --- feedforward block ---
        convw(w_ff2 + (size_t)l * FFD * DIM,     wb + WB_FF2(l), FFD, DIM);
        rmsnorm_split_kernel<<<SEQ, 256>>>(x, gamma_ff + l * DIM, ab);
        bgemm_kernel<true, false, true, true><<<dim3(FFD / 128, SEQ / 128), 256, GEMM_SMEM>>>(
            ab, wb + WB_FF1(l), b_ff1 + (size_t)l * FFD, nullptr, ab2, SEQ, FFD, 3 * DIM);
        bgemm_kernel<true, true, false, false><<<dim3(DIM / 128, SEQ / 128), 256, GEMM_SMEM>>>(
            ab2, wb + WB_FF2(l), b_ff2 + (size_t)l * DIM, x, nullptr, SEQ, DIM, 3 * FFD);
    }

    convw(w_logits, wb + WB_LOGITS, DIM, VOCAB);
    rmsnorm_split_kernel<<<SEQ, 256>>>(x, gamma_final, ab);
    bgemm_kernel<false, false, false, false><<<dim3(VOCAB / 128, SEQ / 128), 256, GEMM_SMEM>>>(
        ab, wb + WB_LOGITS, nullptr, out, nullptr, SEQ, VOCAB, 3 * DIM);
}

// round 6
// speedup vs baseline: 2.0729x; 1.0826x over previous
#include <cuda_runtime.h>
#include <cuda_bf16.h>
#include <cuda_fp16.h>
#include <math.h>
#include <float.h>
#include <stdint.h>

// ---------------- problem constants ----------------
#define SEQ   2048
#define DIM   1024
#define DEPTH 4
#define HEADS 16
#define DH    64
#define FFD   4096
#define VOCAB 32000

// ---------------- scratch (static device globals) ----------------
__device__ float g_x   [SEQ * DIM];                  // residual stream (fp32)
__device__ float g_qkv [SEQ * 3 * DIM];              // qkv projections (fp32)
__device__ __nv_bfloat16 g_ab [SEQ * 3 * DIM];       // split activations (layer GEMMs)
__device__ __nv_bfloat16 g_ab2[SEQ * 3 * FFD];       // split activations for ff2
__device__ __nv_bfloat16 g_wb [133431296ull];        // all split weights (B'=[hi;lo])

// weight offsets in g_wb (2-byte elements)
#define WB_QKV(l)  ((size_t)(l) * 6291456ull)
#define WB_OUT(l)  (25165824ull + (size_t)(l) * 2097152ull)
#define WB_FF1(l)  (33554432ull + (size_t)(l) * 8388608ull)
#define WB_FF2(l)  (67108864ull + (size_t)(l) * 8388608ull)
#define WB_LOGITS  100663296ull

// ---------------- helpers ----------------
__device__ __forceinline__ uint32_t smem_u32(const void* p) {
    return (uint32_t)__cvta_generic_to_shared(p);
}
__device__ __forceinline__ void cp16(uint32_t s, const void* g) {
    asm volatile("cp.async.cg.shared.global [%0], [%1], 16;" :: "r"(s), "l"(g));
}

// ---------------- weight split bf16: fp32[K,N] -> [Bhi ; Blo] bf16[2K,N] ----
__global__ void __launch_bounds__(256) convw_kernel(const float4* __restrict__ w,
                                                    __nv_bfloat16* __restrict__ o,
                                                    long long KN4) {
    long long idx = (long long)blockIdx.x * 256 + threadIdx.x;
    if (idx >= KN4) return;
    float4 v = w[idx];
    union { unsigned short u[4]; uint2 p; } hi4, lo4;
    float vv[4] = {v.x, v.y, v.z, v.w};
    #pragma unroll
    for (int e = 0; e < 4; e++) {
        __nv_bfloat16 hi = __float2bfloat16_rn(vv[e]);
        __nv_bfloat16 lo = __float2bfloat16_rn(vv[e] - __bfloat162float(hi));
        hi4.u[e] = *(unsigned short*)&hi;
        lo4.u[e] = *(unsigned short*)&lo;
    }
    long long KN = KN4 * 4;
    *(uint2*)(o + 4 * idx)      = hi4.p;
    *(uint2*)(o + KN + 4 * idx) = lo4.p;
}

// ---------------- weight conv fp16 (logits, hi only): fp32[K,N] -> fp16[K,N] ----
__global__ void __launch_bounds__(256) convw_f16_kernel(const float4* __restrict__ w,
                                                        __half* __restrict__ o,
                                                        long long KN4) {
    long long idx = (long long)blockIdx.x * 256 + threadIdx.x;
    if (idx >= KN4) return;
    float4 v = w[idx];
    union { __half u[4]; uint2 p; } h4;
    h4.u[0] = __float2half_rn(v.x); h4.u[1] = __float2half_rn(v.y);
    h4.u[2] = __float2half_rn(v.z); h4.u[3] = __float2half_rn(v.w);
    *(uint2*)(o + 4 * idx) = h4.p;
}

// ---------------- embed ----------------
__global__ void __launch_bounds__(256) embed_kernel(const int* __restrict__ tokens,
                                                    const float* __restrict__ emb,
                                                    float* __restrict__ x) {
    int idx = blockIdx.x * 256 + threadIdx.x;
    int row = idx >> 10;
    int d   = idx & 1023;
    x[idx] = emb[(size_t)tokens[row] * DIM + d];
}

// ---------------- rmsnorm + split bf16 3-term: A' = [hi | lo | hi], stride 3*DIM ----
__global__ void __launch_bounds__(256) rmsnorm_split_kernel(const float* __restrict__ x,
                                                            const float* __restrict__ gamma,
                                                            __nv_bfloat16* __restrict__ ab) {
    int row = blockIdx.x;
    const float* xr = x + (size_t)row * DIM;
    float ss = 0.f;
    for (int i = threadIdx.x; i < DIM; i += 256) { float v = xr[i]; ss += v * v; }
    __shared__ float red[256];
    red[threadIdx.x] = ss;
    __syncthreads();
    for (int s = 128; s > 0; s >>= 1) {
        if (threadIdx.x < s) red[threadIdx.x] += red[threadIdx.x + s];
        __syncthreads();
    }
    float scale = 32.0f / fmaxf(sqrtf(red[0]), 1e-12f);
    __nv_bfloat16* ar = ab + (size_t)row * (3 * DIM);
    for (int i = threadIdx.x; i < DIM; i += 256) {
        float v = xr[i] * scale * gamma[i];
        __nv_bfloat16 hi = __float2bfloat16_rn(v);
        __nv_bfloat16 lo = __float2bfloat16_rn(v - __bfloat162float(hi));
        ar[i] = hi;
        ar[DIM + i] = lo;
        ar[2 * DIM + i] = hi;
    }
}

// ---------------- rmsnorm + split fp16 2-term: A' = [hi | lo], stride 2*DIM ----
__global__ void __launch_bounds__(256) rmsnorm_split_f16_kernel(const float* __restrict__ x,
                                                                const float* __restrict__ gamma,
                                                                __half* __restrict__ ab) {
    int row = blockIdx.x;
    const float* xr = x + (size_t)row * DIM;
    float ss = 0.f;
    for (int i = threadIdx.x; i < DIM; i += 256) { float v = xr[i]; ss += v * v; }
    __shared__ float red[256];
    red[threadIdx.x] = ss;
    __syncthreads();
    for (int s = 128; s > 0; s >>= 1) {
        if (threadIdx.x < s) red[threadIdx.x] += red[threadIdx.x + s];
        __syncthreads();
    }
    float scale = 32.0f / fmaxf(sqrtf(red[0]), 1e-12f);
    __half* ar = ab + (size_t)row * (2 * DIM);
    for (int i = threadIdx.x; i < DIM; i += 256) {
        float v = xr[i] * scale * gamma[i];
        __half hi = __float2half_rn(v);
        __half lo = __float2half_rn(v - __half2float(hi));
        ar[i] = hi;
        ar[DIM + i] = lo;
    }
}

// ---------------- rotary on q and k heads (in place in qkv, fp32) ----------------
__global__ void __launch_bounds__(256) rotary_kernel(float* __restrict__ qkv) {
    int idx = blockIdx.x * 256 + threadIdx.x;
    int j    = idx & 31;
    int head = (idx >> 5) & 31;
    int pos  = idx >> 10;
    float inv = powf(10000.0f, -((float)(2 * j)) * (1.0f / 64.0f));
    float f = (float)pos * inv;
    float c = cosf(f), s = sinf(f);
    float* base = qkv + (size_t)pos * (3 * DIM) + head * DH;
    float x1 = base[j], x2 = base[j + 32];
    base[j]      = x1 * c - x2 * s;
    base[j + 32] = x2 * c + x1 * s;
}

// ---------------- tensor-core GEMM, 5-stage cp.async pipeline ----------------
// C[MxN] = A'[M x TERMS*K] @ Bmap; B stored [Bhi;Blo(3t)] or [Bhi(2t)];
// K-step s uses B block (s<Ku ? s : s-Ku). 128x128x32 tiles, 8 warps.
#define LDSM4(R0,R1,R2,R3,addr) \
    asm volatile("ldmatrix.sync.aligned.m8n8.x4.shared.b16 {%0,%1,%2,%3},[%4];" \
        : "=r"(R0),"=r"(R1),"=r"(R2),"=r"(R3) : "r"(addr))
#define LDSM4T(R0,R1,R2,R3,addr) \
    asm volatile("ldmatrix.sync.aligned.m8n8.x4.trans.shared.b16 {%0,%1,%2,%3},[%4];" \
        : "=r"(R0),"=r"(R1),"=r"(R2),"=r"(R3) : "r"(addr))

template<bool F16>
__device__ __forceinline__ void mma_op(float* d, const uint32_t* a, uint32_t b0, uint32_t b1) {
    if (F16)
        asm volatile("mma.sync.aligned.m16n8k16.row.col.f32.f16.f16.f32 "
            "{%0,%1,%2,%3},{%4,%5,%6,%7},{%8,%9},{%0,%1,%2,%3};"
            : "+f"(d[0]),"+f"(d[1]),"+f"(d[2]),"+f"(d[3])
            : "r"(a[0]),"r"(a[1]),"r"(a[2]),"r"(a[3]),"r"(b0),"r"(b1));
    else
        asm volatile("mma.sync.aligned.m16n8k16.row.col.f32.bf16.bf16.f32 "
            "{%0,%1,%2,%3},{%4,%5,%6,%7},{%8,%9},{%0,%1,%2,%3};"
            : "+f"(d[0]),"+f"(d[1]),"+f"(d[2]),"+f"(d[3])
            : "r"(a[0]),"r"(a[1]),"r"(a[2]),"r"(a[3]),"r"(b0),"r"(b1));
}

#define NSTAGE 5
#define A_STG_B 10240                 // 128 rows * 40 stride * 2B
#define B_STG_B 8704                  // 32 rows * 136 stride * 2B
#define SSTG_B  (A_STG_B + B_STG_B)   // 18944 bytes per stage
#define GEMM_SMEM (NSTAGE * SSTG_B)   // 94720 bytes

// grid: x = M tiles (fast-varying -> B column slice L2-reused), y = N tiles
template<int TERMS, bool F16, bool BIAS, bool RES, bool GELU, bool SPLIT>
__global__ void __launch_bounds__(256)
bgemm_kernel(const __nv_bfloat16* __restrict__ A,
             const __nv_bfloat16* __restrict__ B,
             const float* __restrict__ bias,
             float* __restrict__ C,
             __nv_bfloat16* __restrict__ Cs,
             int N, int Ku)      // Ku = K / 32 (one term-block in 32-col steps)
{
    extern __shared__ __align__(16) __nv_bfloat16 sm[];
    uint32_t sbase = smem_u32(sm);

    int tid  = threadIdx.x;
    int lane = tid & 31;
    int warp = tid >> 5;
    int wm = warp >> 2;       // 0..1
    int wn = warp & 3;        // 0..3
    int bm = blockIdx.x * 128;
    int bn = blockIdx.y * 128;
    int Astride = TERMS * Ku * 32;   // elements per A row

    // global load assignments (2 x 16B for A, 2 x 16B for B per thread)
    int ra0 = tid >> 2;            // 0..63
    int ca0 = (tid & 3) * 8;       // 0,8,16,24
    int rb0 = tid >> 4;            // 0..15
    int cb  = (tid & 15) * 8;      // 0..120

    const char* gA0 = (const char*)(A + (size_t)(bm + ra0)      * Astride + ca0);
    const char* gA1 = (const char*)(A + (size_t)(bm + ra0 + 64) * Astride + ca0);
    const char* gB0 = (const char*)(B + (size_t)(rb0)      * N + bn + cb);
    const char* gB1 = (const char*)(B + (size_t)(rb0 + 16) * N + bn + cb);
    size_t bStep = (size_t)64 * N;   // bytes per 32-row K-step of B

    uint32_t sA0off = (uint32_t)((ra0 * 40 + ca0) * 2);
    uint32_t sA1off = (uint32_t)(((ra0 + 64) * 40 + ca0) * 2);
    uint32_t sB0off = (uint32_t)(A_STG_B + (rb0 * 136 + cb) * 2);
    uint32_t sB1off = (uint32_t)(A_STG_B + ((rb0 + 16) * 136 + cb) * 2);

    uint32_t aFrag = (uint32_t)(((wm * 64 + (lane & 15)) * 40 + (lane >> 4) * 8) * 2);
    uint32_t bFrag = (uint32_t)(A_STG_B + ((lane & 15) * 136 + wn * 32 + (lane >> 4) * 8) * 2);

    float acc[4][4][4];
    #pragma unroll
    for (int i = 0; i < 4; i++)
        #pragma unroll
        for (int j = 0; j < 4; j++)
            #pragma unroll
            for (int k = 0; k < 4; k++) acc[i][j][k] = 0.f;

    int steps = TERMS * Ku;

    auto load_stage = [&](int t) {
        uint32_t so = sbase + (uint32_t)(t % NSTAGE) * SSTG_B;
        int bs = (t < Ku) ? t : t - Ku;          // block map: [hi, hi(3t)/.., lo]
        size_t advA = (size_t)t * 64;
        size_t advB = (size_t)bs * bStep;
        cp16(so + sA0off, gA0 + advA);
        cp16(so + sA1off, gA1 + advA);
        cp16(so + sB0off, gB0 + advB);
        cp16(so + sB1off, gB1 + advB);
        asm volatile("cp.async.commit_group;" ::: "memory");
    };

    #pragma unroll
    for (int t = 0; t < NSTAGE - 1; t++) load_stage(t);

    for (int s = 0; s < steps; s++) {
        int rem = steps - 1 - s;
        if (rem >= 3)      asm volatile("cp.async.wait_group 3;" ::: "memory");
        else if (rem == 2) asm volatile("cp.async.wait_group 2;" ::: "memory");
        else if (rem == 1) asm volatile("cp.async.wait_group 1;" ::: "memory");
        else               asm volatile("cp.async.wait_group 0;" ::: "memory");
        __syncthreads();

        if (s + NSTAGE - 1 < steps) load_stage(s + NSTAGE - 1);

        uint32_t stg = sbase + (uint32_t)(s % NSTAGE) * SSTG_B;
        uint32_t aB = stg + aFrag;
        uint32_t bB = stg + bFrag;
        #pragma unroll
        for (int kk = 0; kk < 2; kk++) {
            uint32_t af[4][4], bf[2][4];
            #pragma unroll
            for (int mt = 0; mt < 4; mt++) {
                uint32_t addr = aB + mt * (16 * 40 * 2) + kk * 32;
                LDSM4(af[mt][0], af[mt][1], af[mt][2], af[mt][3], addr);
            }
            #pragma unroll
            for (int p = 0; p < 2; p++) {
                uint32_t addr = bB + p * 32 + kk * (16 * 136 * 2);
                LDSM4T(bf[p][0], bf[p][1], bf[p][2], bf[p][3], addr);
            }
            #pragma unroll
            for (int mt = 0; mt < 4; mt++) {
                #pragma unroll
                for (int nt = 0; nt < 4; nt++) {
                    uint32_t b0 = bf[nt >> 1][(nt & 1) * 2];
                    uint32_t b1 = bf[nt >> 1][(nt & 1) * 2 + 1];
                    mma_op<F16>(acc[mt][nt], af[mt], b0, b1);
                }
            }
        }
    }

    // epilogue
    int row0 = bm + wm * 64;
    int col0 = bn + wn * 32;
    #pragma unroll
    for (int mt = 0; mt < 4; mt++) {
        #pragma unroll
        for (int nt = 0; nt < 4; nt++) {
            int r = row0 + mt * 16 + (lane >> 2);
            int c = col0 + nt * 8 + (lane & 3) * 2;
            #pragma unroll
            for (int half = 0; half < 2; half++) {
                int rr = r + half * 8;
                #pragma unroll
                for (int e = 0; e < 2; e++) {
                    float val = acc[mt][nt][half * 2 + e];
                    int cc = c + e;
                    if (BIAS) val += bias[cc];
                    if (GELU) val = 0.5f * val * (1.0f + erff(val * 0.70710678118654752f));
                    if (SPLIT) {
                        __nv_bfloat16 hi = __float2bfloat16_rn(val);
                        __nv_bfloat16 lo = __float2bfloat16_rn(val - __bfloat162float(hi));
                        size_t base = (size_t)rr * (3 * (size_t)N);
                        Cs[base + cc] = hi;
                        Cs[base + N + cc] = lo;
                        Cs[base + 2 * (size_t)N + cc] = hi;
                    } else {
                        size_t off = (size_t)rr * N + cc;
                        if (RES) val += C[off];
                        C[off] = val;
                    }
                }
            }
        }
    }
}

// ---------------- fused flash attention (fp32, causal) ----------------
__global__ void __launch_bounds__(256) flash_kernel(const float* __restrict__ qkv,
                                                    __nv_bfloat16* __restrict__ ab) {
    extern __shared__ float fsm[];
    float* Qs = fsm;                   // [64][64]  (d-major)
    float* Ks = Qs + 64 * 64;          // [64][64]  (d-major)
    float* Vs = Ks + 64 * 64;          // [64][68]
    float* Ps = Vs + 64 * 68;          // [64][65]

    int br = gridDim.x - 1 - blockIdx.x;
    int h  = blockIdx.y;
    int tid = threadIdx.x;
    int tx = tid & 15, ty = tid >> 4;

    const float* qb = qkv + (size_t)br * 64 * (3 * DIM) + h * DH;
    #pragma unroll
    for (int l = 0; l < 4; l++) {
        int i = tid + l * 256;
        int r  = i >> 4;
        int d4 = (i & 15) * 4;
        float4 v = *(const float4*)(qb + (size_t)r * (3 * DIM) + d4);
        Qs[(d4 + 0) * 64 + r] = v.x * 0.125f;
        Qs[(d4 + 1) * 64 + r] = v.y * 0.125f;
        Qs[(d4 + 2) * 64 + r] = v.z * 0.125f;
        Qs[(d4 + 3) * 64 + r] = v.w * 0.125f;
    }

    float run_max[4], run_sum[4], O[4][4];
    #pragma unroll
    for (int r = 0; r < 4; r++) {
        run_max[r] = -FLT_MAX; run_sum[r] = 0.f;
        #pragma unroll
        for (int c = 0; c < 4; c++) O[r][c] = 0.f;
    }

    for (int kb = 0; kb <= br; kb++) {
        __syncthreads();
        const float* kbp = qkv + (size_t)kb * 64 * (3 * DIM) + (HEADS + h) * DH;
        const float* vbp = qkv + (size_t)kb * 64 * (3 * DIM) + (2 * HEADS + h) * DH;
        #pragma unroll
        for (int l = 0; l < 4; l++) {
            int i = tid + l * 256;
            int r  = i >> 4;
            int d4 = (i & 15) * 4;
            float4 w = *(const float4*)(kbp + (size_t)r * (3 * DIM) + d4);
            Ks[(d4 + 0) * 64 + r] = w.x; Ks[(d4 + 1) * 64 + r] = w.y;
            Ks[(d4 + 2) * 64 + r] = w.z; Ks[(d4 + 3) * 64 + r] = w.w;
            float4 u = *(const float4*)(vbp + (size_t)r * (3 * DIM) + d4);
            *(float4*)(Vs + r * 68 + d4) = u;
        }
        __syncthreads();

        float acc[4][4];
        #pragma unroll
        for (int r = 0; r < 4; r++)
            #pragma unroll
            for (int c = 0; c < 4; c++) acc[r][c] = 0.f;
        #pragma unroll 4
        for (int d = 0; d < 64; d++) {
            float4 rq = *(const float4*)(Qs + d * 64 + ty * 4);
            float4 rk = *(const float4*)(Ks + d * 64 + tx * 4);
            float qa[4] = {rq.x, rq.y, rq.z, rq.w};
            float ka[4] = {rk.x, rk.y, rk.z, rk.w};
            #pragma unroll
            for (int r = 0; r < 4; r++)
                #pragma unroll
                for (int c = 0; c < 4; c++)
                    acc[r][c] += qa[r] * ka[c];
        }

        if (kb == br) {
            #pragma unroll
            for (int r = 0; r < 4; r++) {
                int gi = ty * 4 + r;
                #pragma unroll
                for (int c = 0; c < 4; c++) {
                    int gj = tx * 4 + c;
                    if (gj > gi) acc[r][c] = -FLT_MAX;
                }
            }
        }

        float alpha[4];
        #pragma unroll
        for (int r = 0; r < 4; r++) {
            float mt = fmaxf(fmaxf(acc[r][0], acc[r][1]), fmaxf(acc[r][2], acc[r][3]));
            #pragma unroll
            for (int msk = 8; msk > 0; msk >>= 1)
                mt = fmaxf(mt, __shfl_xor_sync(0xffffffffu, mt, msk));
            float nm = fmaxf(run_max[r], mt);
            alpha[r] = expf(run_max[r] - nm);
            run_max[r] = nm;
            float ps = 0.f;
            #pragma unroll
            for (int c = 0; c < 4; c++) {
                float p = expf(acc[r][c] - nm);
                acc[r][c] = p;
                ps += p;
            }
            #pragma unroll
            for (int msk = 8; msk > 0; msk >>= 1)
                ps += __shfl_xor_sync(0xffffffffu, ps, msk);
            run_sum[r] = run_sum[r] * alpha[r] + ps;
        }

        #pragma unroll
        for (int r = 0; r < 4; r++)
            #pragma unroll
            for (int c = 0; c < 4; c++)
                Ps[(tx * 4 + c) * 65 + ty * 4 + r] = acc[r][c];
        __syncthreads();

        #pragma unroll
        for (int r = 0; r < 4; r++)
            #pragma unroll
            for (int c = 0; c < 4; c++) O[r][c] *= alpha[r];
        #pragma unroll 4
        for (int jj = 0; jj < 64; jj++) {
            float pr[4];
            #pragma unroll
            for (int r = 0; r < 4; r++) pr[r] = Ps[jj * 65 + ty * 4 + r];
            float4 rv = *(const float4*)(Vs + jj * 68 + tx * 4);
            float vv[4] = {rv.x, rv.y, rv.z, rv.w};
            #pragma unroll
            for (int r = 0; r < 4; r++)
                #pragma unroll
                for (int c = 0; c < 4; c++)
                    O[r][c] += pr[r] * vv[c];
        }
    }

    #pragma unroll
    for (int r = 0; r < 4; r++) {
        int gi = br * 64 + ty * 4 + r;
        float inv = 1.0f / run_sum[r];
        size_t base = (size_t)gi * (3 * DIM);
        #pragma unroll
        for (int c = 0; c < 4; c++) {
            int col = h * DH + tx * 4 + c;
            float v = O[r][c] * inv;
            __nv_bfloat16 hi = __float2bfloat16_rn(v);
            __nv_bfloat16 lo = __float2bfloat16_rn(v - __bfloat162float(hi));
            ab[base + col] = hi;
            ab[base + DIM + col] = lo;
            ab[base + 2 * DIM + col] = hi;
        }
    }
}

#define FLASH_SMEM ((64 * 64 + 64 * 64 + 64 * 68 + 64 * 65) * 4)

// ---------------- launch ----------------
static inline void convw(const float* src, __nv_bfloat16* dst, long long K, long long N) {
    long long KN4 = K * N / 4;
    convw_kernel<<<(unsigned)((KN4 + 255) / 256), 256>>>((const float4*)src, dst, KN4);
}

extern "C" void kernel_launch(void* const* d_in, const int* in_sizes, int n_in,
                              void* d_out, int out_size) {
    const int*   tokens      = (const int*)  d_in[0];
    const float* emb         = (const float*)d_in[1];
    const float* gamma_attn  = (const float*)d_in[2];
    const float* w_qkv       = (const float*)d_in[3];
    const float* w_out       = (const float*)d_in[4];
    const float* gamma_ff    = (const float*)d_in[5];
    const float* w_ff1       = (const float*)d_in[6];
    const float* b_ff1       = (const float*)d_in[7];
    const float* w_ff2       = (const float*)d_in[8];
    const float* b_ff2       = (const float*)d_in[9];
    const float* gamma_final = (const float*)d_in[10];
    const float* w_logits    = (const float*)d_in[11];
    float* out = (float*)d_out;

    float *x, *qkv;
    __nv_bfloat16 *ab, *ab2, *wb;
    cudaGetSymbolAddress((void**)&x,   g_x);
    cudaGetSymbolAddress((void**)&qkv, g_qkv);
    cudaGetSymbolAddress((void**)&ab,  g_ab);
    cudaGetSymbolAddress((void**)&ab2, g_ab2);
    cudaGetSymbolAddress((void**)&wb,  g_wb);

    cudaFuncSetAttribute(flash_kernel, cudaFuncAttributeMaxDynamicSharedMemorySize,
                         FLASH_SMEM);
    cudaFuncSetAttribute(bgemm_kernel<3, false, false, false, false, false>,
                         cudaFuncAttributeMaxDynamicSharedMemorySize, GEMM_SMEM);
    cudaFuncSetAttribute(bgemm_kernel<3, false, false, true, false, false>,
                         cudaFuncAttributeMaxDynamicSharedMemorySize, GEMM_SMEM);
    cudaFuncSetAttribute(bgemm_kernel<3, false, true, false, true, true>,
                         cudaFuncAttributeMaxDynamicSharedMemorySize, GEMM_SMEM);
    cudaFuncSetAttribute(bgemm_kernel<3, false, true, true, false, false>,
                         cudaFuncAttributeMaxDynamicSharedMemorySize, GEMM_SMEM);
    cudaFuncSetAttribute(bgemm_kernel<2, true, false, false, false, false>,
                         cudaFuncAttributeMaxDynamicSharedMemorySize, GEMM_SMEM);

    // launch order: index 3 = qkv bgemm (for ncu sampling)
    embed_kernel<<<SEQ * DIM / 256, 256>>>(tokens, emb, x);                        // 0
    convw(w_qkv, wb + WB_QKV(0), DIM, 3 * DIM);                                    // 1
    rmsnorm_split_kernel<<<SEQ, 256>>>(x, gamma_attn, ab);                         // 2

    for (int l = 0; l < DEPTH; l++) {
        if (l > 0) {
            convw(w_qkv + (size_t)l * DIM * 3 * DIM, wb + WB_QKV(l), DIM, 3 * DIM);
            rmsnorm_split_kernel<<<SEQ, 256>>>(x, gamma_attn + l * DIM, ab);
        }
        bgemm_kernel<3, false, false, false, false, false>
            <<<dim3(SEQ / 128, 3 * DIM / 128), 256, GEMM_SMEM>>>(
            ab, wb + WB_QKV(l), nullptr, qkv, nullptr, 3 * DIM, DIM / 32);         // l=0: 3
        rotary_kernel<<<SEQ * 1024 / 256, 256>>>(qkv);
        flash_kernel<<<dim3(SEQ / 64, HEADS), 256, FLASH_SMEM>>>(qkv, ab);
        convw(w_out + (size_t)l * DIM * DIM, wb + WB_OUT(l), DIM, DIM);
        bgemm_kernel<3, false, false, true, false, false>
            <<<dim3(SEQ / 128, DIM / 128), 256, GEMM_SMEM>>>(
            ab, wb + WB_OUT(l), nullptr, x, nullptr, DIM, DIM / 32);
        // --- feedforward block ---
        rmsnorm_split_kernel<<<SEQ, 256>>>(x, gamma_ff + l * DIM, ab);
        convw(w_ff1 + (size_t)l * DIM * FFD, wb + WB_FF1(l), DIM, FFD);
        bgemm_kernel<3, false, true, false, true, true>
            <<<dim3(SEQ / 128, FFD / 128), 256, GEMM_SMEM>>>(
            ab, wb + WB_FF1(l), b_ff1 + (size_t)l * FFD, nullptr, ab2, FFD, DIM / 32);
        convw(w_ff2 + (size_t)l * FFD * DIM, wb + WB_FF2(l), FFD, DIM);
        bgemm_kernel<3, false, true, true, false, false>
            <<<dim3(SEQ / 128, DIM / 128), 256, GEMM_SMEM>>>(
            ab2, wb + WB_FF2(l), b_ff2 + (size_t)l * DIM, x, nullptr, DIM, FFD / 32);
    }

    // final norm + fp16 2-term logits GEMM
    {
        long long KN4 = (long long)DIM * VOCAB / 4;
        convw_f16_kernel<<<(unsigned)((KN4 + 255) / 256), 256>>>(
            (const float4*)w_logits, (__half*)(wb + WB_LOGITS), KN4);
    }
    rmsnorm_split_f16_kernel<<<SEQ, 256>>>(x, gamma_final, (__half*)ab);
    bgemm_kernel<2, true, false, false, false, false>
        <<<dim3(SEQ / 128, VOCAB / 128), 256, GEMM_SMEM>>>(
        ab, wb + WB_LOGITS, nullptr, out, nullptr, VOCAB, DIM / 32);
}

// round 7
// speedup vs baseline: 2.1940x; 1.0584x over previous
#include <cuda_runtime.h>
#include <cuda_bf16.h>
#include <cuda_fp16.h>
#include <math.h>
#include <float.h>
#include <stdint.h>

// ---------------- problem constants ----------------
#define SEQ   2048
#define DIM   1024
#define DEPTH 4
#define HEADS 16
#define DH    64
#define FFD   4096
#define VOCAB 32000

// ---------------- scratch (static device globals) ----------------
__device__ float g_x   [SEQ * DIM];                  // residual stream (fp32)
__device__ float g_qkv [SEQ * 3 * DIM];              // qkv projections (fp32)
__device__ __nv_bfloat16 g_ab [SEQ * 3 * DIM];       // split activations (layer GEMMs)
__device__ __nv_bfloat16 g_ab2[SEQ * 3 * FFD];       // split activations for ff2
__device__ __nv_bfloat16 g_wb [133431296ull];        // all split weights (B'=[hi;lo])

// weight offsets in g_wb (2-byte elements)
#define WB_QKV(l)  ((size_t)(l) * 6291456ull)
#define WB_OUT(l)  (25165824ull + (size_t)(l) * 2097152ull)
#define WB_FF1(l)  (33554432ull + (size_t)(l) * 8388608ull)
#define WB_FF2(l)  (67108864ull + (size_t)(l) * 8388608ull)
#define WB_LOGITS  100663296ull

// ---------------- helpers ----------------
__device__ __forceinline__ uint32_t smem_u32(const void* p) {
    return (uint32_t)__cvta_generic_to_shared(p);
}
__device__ __forceinline__ void cp16(uint32_t s, const void* g) {
    asm volatile("cp.async.cg.shared.global [%0], [%1], 16;" :: "r"(s), "l"(g));
}

// ---------------- weight split bf16: fp32[K,N] -> [Bhi ; Blo] bf16[2K,N] ----
__global__ void __launch_bounds__(256) convw_kernel(const float4* __restrict__ w,
                                                    __nv_bfloat16* __restrict__ o,
                                                    long long KN4) {
    long long idx = (long long)blockIdx.x * 256 + threadIdx.x;
    if (idx >= KN4) return;
    float4 v = w[idx];
    union { unsigned short u[4]; uint2 p; } hi4, lo4;
    float vv[4] = {v.x, v.y, v.z, v.w};
    #pragma unroll
    for (int e = 0; e < 4; e++) {
        __nv_bfloat16 hi = __float2bfloat16_rn(vv[e]);
        __nv_bfloat16 lo = __float2bfloat16_rn(vv[e] - __bfloat162float(hi));
        hi4.u[e] = *(unsigned short*)&hi;
        lo4.u[e] = *(unsigned short*)&lo;
    }
    long long KN = KN4 * 4;
    *(uint2*)(o + 4 * idx)      = hi4.p;
    *(uint2*)(o + KN + 4 * idx) = lo4.p;
}

// ---------------- weight conv fp16 (logits, hi only) ----------------
__global__ void __launch_bounds__(256) convw_f16_kernel(const float4* __restrict__ w,
                                                        __half* __restrict__ o,
                                                        long long KN4) {
    long long idx = (long long)blockIdx.x * 256 + threadIdx.x;
    if (idx >= KN4) return;
    float4 v = w[idx];
    union { __half u[4]; uint2 p; } h4;
    h4.u[0] = __float2half_rn(v.x); h4.u[1] = __float2half_rn(v.y);
    h4.u[2] = __float2half_rn(v.z); h4.u[3] = __float2half_rn(v.w);
    *(uint2*)(o + 4 * idx) = h4.p;
}

// ---------------- embed ----------------
__global__ void __launch_bounds__(256) embed_kernel(const int* __restrict__ tokens,
                                                    const float* __restrict__ emb,
                                                    float* __restrict__ x) {
    int idx = blockIdx.x * 256 + threadIdx.x;
    int row = idx >> 10;
    int d   = idx & 1023;
    x[idx] = emb[(size_t)tokens[row] * DIM + d];
}

// ---------------- rmsnorm + split bf16 3-term: A' = [hi | lo | hi] ----
__global__ void __launch_bounds__(256) rmsnorm_split_kernel(const float* __restrict__ x,
                                                            const float* __restrict__ gamma,
                                                            __nv_bfloat16* __restrict__ ab) {
    int row = blockIdx.x;
    const float* xr = x + (size_t)row * DIM;
    float ss = 0.f;
    for (int i = threadIdx.x; i < DIM; i += 256) { float v = xr[i]; ss += v * v; }
    __shared__ float red[256];
    red[threadIdx.x] = ss;
    __syncthreads();
    for (int s = 128; s > 0; s >>= 1) {
        if (threadIdx.x < s) red[threadIdx.x] += red[threadIdx.x + s];
        __syncthreads();
    }
    float scale = 32.0f / fmaxf(sqrtf(red[0]), 1e-12f);
    __nv_bfloat16* ar = ab + (size_t)row * (3 * DIM);
    for (int i = threadIdx.x; i < DIM; i += 256) {
        float v = xr[i] * scale * gamma[i];
        __nv_bfloat16 hi = __float2bfloat16_rn(v);
        __nv_bfloat16 lo = __float2bfloat16_rn(v - __bfloat162float(hi));
        ar[i] = hi;
        ar[DIM + i] = lo;
        ar[2 * DIM + i] = hi;
    }
}

// ---------------- rmsnorm + split fp16 2-term: A' = [hi | lo] ----
__global__ void __launch_bounds__(256) rmsnorm_split_f16_kernel(const float* __restrict__ x,
                                                                const float* __restrict__ gamma,
                                                                __half* __restrict__ ab) {
    int row = blockIdx.x;
    const float* xr = x + (size_t)row * DIM;
    float ss = 0.f;
    for (int i = threadIdx.x; i < DIM; i += 256) { float v = xr[i]; ss += v * v; }
    __shared__ float red[256];
    red[threadIdx.x] = ss;
    __syncthreads();
    for (int s = 128; s > 0; s >>= 1) {
        if (threadIdx.x < s) red[threadIdx.x] += red[threadIdx.x + s];
        __syncthreads();
    }
    float scale = 32.0f / fmaxf(sqrtf(red[0]), 1e-12f);
    __half* ar = ab + (size_t)row * (2 * DIM);
    for (int i = threadIdx.x; i < DIM; i += 256) {
        float v = xr[i] * scale * gamma[i];
        __half hi = __float2half_rn(v);
        __half lo = __float2half_rn(v - __half2float(hi));
        ar[i] = hi;
        ar[DIM + i] = lo;
    }
}

// ---------------- rotary on q and k heads (in place in qkv, fp32) ----------------
__global__ void __launch_bounds__(256) rotary_kernel(float* __restrict__ qkv) {
    int idx = blockIdx.x * 256 + threadIdx.x;
    int j    = idx & 31;
    int head = (idx >> 5) & 31;
    int pos  = idx >> 10;
    float inv = powf(10000.0f, -((float)(2 * j)) * (1.0f / 64.0f));
    float f = (float)pos * inv;
    float c = cosf(f), s = sinf(f);
    float* base = qkv + (size_t)pos * (3 * DIM) + head * DH;
    float x1 = base[j], x2 = base[j + 32];
    base[j]      = x1 * c - x2 * s;
    base[j + 32] = x2 * c + x1 * s;
}

// ---------------- tensor-core GEMM: K-chunk 64, 3 stages, fragment double-buffer ----
#define LDSM4(R0,R1,R2,R3,addr) \
    asm volatile("ldmatrix.sync.aligned.m8n8.x4.shared.b16 {%0,%1,%2,%3},[%4];" \
        : "=r"(R0),"=r"(R1),"=r"(R2),"=r"(R3) : "r"(addr))
#define LDSM4T(R0,R1,R2,R3,addr) \
    asm volatile("ldmatrix.sync.aligned.m8n8.x4.trans.shared.b16 {%0,%1,%2,%3},[%4];" \
        : "=r"(R0),"=r"(R1),"=r"(R2),"=r"(R3) : "r"(addr))

template<bool F16>
__device__ __forceinline__ void mma_op(float* d, const uint32_t* a, uint32_t b0, uint32_t b1) {
    if (F16)
        asm volatile("mma.sync.aligned.m16n8k16.row.col.f32.f16.f16.f32 "
            "{%0,%1,%2,%3},{%4,%5,%6,%7},{%8,%9},{%0,%1,%2,%3};"
            : "+f"(d[0]),"+f"(d[1]),"+f"(d[2]),"+f"(d[3])
            : "r"(a[0]),"r"(a[1]),"r"(a[2]),"r"(a[3]),"r"(b0),"r"(b1));
    else
        asm volatile("mma.sync.aligned.m16n8k16.row.col.f32.bf16.bf16.f32 "
            "{%0,%1,%2,%3},{%4,%5,%6,%7},{%8,%9},{%0,%1,%2,%3};"
            : "+f"(d[0]),"+f"(d[1]),"+f"(d[2]),"+f"(d[3])
            : "r"(a[0]),"r"(a[1]),"r"(a[2]),"r"(a[3]),"r"(b0),"r"(b1));
}

#define A_STG_B 18432                 // 128 rows * 72 stride * 2B (K=64 chunk)
#define B_STG_B 17408                 // 64 rows * 136 stride * 2B
#define SSTG_B  (A_STG_B + B_STG_B)   // 35840 bytes per stage
#define GEMM_SMEM (3 * SSTG_B)        // 107520 bytes

// grid: x = M tiles (fast -> B slice L2-reused), y = N tiles. 128x128 block tile.
template<int TERMS, bool F16, bool BIAS, bool RES, bool GELU, bool SPLIT>
__global__ void __launch_bounds__(256, 2)
bgemm_kernel(const __nv_bfloat16* __restrict__ A,
             const __nv_bfloat16* __restrict__ B,
             const float* __restrict__ bias,
             float* __restrict__ C,
             __nv_bfloat16* __restrict__ Cs,
             int N, int Ku64)     // Ku64 = K / 64 per term
{
    extern __shared__ __align__(16) __nv_bfloat16 sm[];
    uint32_t sbase = smem_u32(sm);

    int tid  = threadIdx.x;
    int lane = tid & 31;
    int warp = tid >> 5;
    int wm = warp >> 2;       // 0..1
    int wn = warp & 3;        // 0..3
    int bm = blockIdx.x * 128;
    int bn = blockIdx.y * 128;
    int Astride = TERMS * Ku64 * 64;   // elements per A row

    const char* gAbase = (const char*)(A + (size_t)bm * Astride);
    const char* gBbase = (const char*)(B + bn);

    uint32_t aFrag = (uint32_t)(((wm * 64 + (lane & 15)) * 72 + (lane >> 4) * 8) * 2);
    uint32_t bFrag = (uint32_t)(A_STG_B + ((lane & 15) * 136 + wn * 32 + (lane >> 4) * 8) * 2);

    float acc[4][4][4];
    #pragma unroll
    for (int i = 0; i < 4; i++)
        #pragma unroll
        for (int j = 0; j < 4; j++)
            #pragma unroll
            for (int k = 0; k < 4; k++) acc[i][j][k] = 0.f;

    int steps = TERMS * Ku64;

    auto load_stage = [&](int t) {
        uint32_t so = sbase + (uint32_t)(t % 3) * SSTG_B;
        int bs = (t < Ku64) ? t : t - Ku64;   // [hi, hi(term2), lo] block map
        const char* aP = gAbase + (size_t)t * 128;            // 64 halves per step
        const char* bP = gBbase + (size_t)bs * ((size_t)N * 128);
        #pragma unroll
        for (int j = 0; j < 4; j++) {
            int i = tid + j * 256;
            cp16(so + (uint32_t)(((i >> 3) * 72 + (i & 7) * 8) * 2),
                 aP + (size_t)(i >> 3) * Astride * 2 + (i & 7) * 16);
            cp16(so + (uint32_t)(A_STG_B + ((i >> 4) * 136 + (i & 15) * 8) * 2),
                 bP + (size_t)(i >> 4) * N * 2 + (i & 15) * 16);
        }
        asm volatile("cp.async.commit_group;" ::: "memory");
    };

    load_stage(0);
    load_stage(1);

    uint32_t af[2][16], bf[2][8];

    auto ldsA = [&](uint32_t* f, uint32_t stg, int kk) {
        #pragma unroll
        for (int mt = 0; mt < 4; mt++) {
            uint32_t addr = stg + aFrag + mt * (16 * 72 * 2) + kk * 32;
            LDSM4(f[mt * 4 + 0], f[mt * 4 + 1], f[mt * 4 + 2], f[mt * 4 + 3], addr);
        }
    };
    auto ldsB = [&](uint32_t* f, uint32_t stg, int kk) {
        #pragma unroll
        for (int p = 0; p < 2; p++) {
            uint32_t addr = stg + bFrag + p * 32 + kk * (16 * 136 * 2);
            LDSM4T(f[p * 4 + 0], f[p * 4 + 1], f[p * 4 + 2], f[p * 4 + 3], addr);
        }
    };

    for (int t = 0; t < steps; t++) {
        if (t + 1 < steps) asm volatile("cp.async.wait_group 1;" ::: "memory");
        else               asm volatile("cp.async.wait_group 0;" ::: "memory");
        __syncthreads();
        if (t + 2 < steps) load_stage(t + 2);

        uint32_t stg = sbase + (uint32_t)(t % 3) * SSTG_B;
        ldsA(af[0], stg, 0);
        ldsB(bf[0], stg, 0);
        #pragma unroll
        for (int kk = 0; kk < 4; kk++) {
            int cur = kk & 1, nxt = cur ^ 1;
            if (kk < 3) { ldsA(af[nxt], stg, kk + 1); ldsB(bf[nxt], stg, kk + 1); }
            #pragma unroll
            for (int mt = 0; mt < 4; mt++) {
                #pragma unroll
                for (int nt = 0; nt < 4; nt++) {
                    uint32_t b0 = bf[cur][(nt >> 1) * 4 + (nt & 1) * 2];
                    uint32_t b1 = bf[cur][(nt >> 1) * 4 + (nt & 1) * 2 + 1];
                    mma_op<F16>(acc[mt][nt], &af[cur][mt * 4], b0, b1);
                }
            }
        }
    }

    // epilogue
    int row0 = bm + wm * 64;
    int col0 = bn + wn * 32;
    #pragma unroll
    for (int mt = 0; mt < 4; mt++) {
        #pragma unroll
        for (int nt = 0; nt < 4; nt++) {
            int r = row0 + mt * 16 + (lane >> 2);
            int c = col0 + nt * 8 + (lane & 3) * 2;
            #pragma unroll
            for (int half = 0; half < 2; half++) {
                int rr = r + half * 8;
                #pragma unroll
                for (int e = 0; e < 2; e++) {
                    float val = acc[mt][nt][half * 2 + e];
                    int cc = c + e;
                    if (BIAS) val += bias[cc];
                    if (GELU) val = 0.5f * val * (1.0f + erff(val * 0.70710678118654752f));
                    if (SPLIT) {
                        __nv_bfloat16 hi = __float2bfloat16_rn(val);
                        __nv_bfloat16 lo = __float2bfloat16_rn(val - __bfloat162float(hi));
                        size_t base = (size_t)rr * (3 * (size_t)N);
                        Cs[base + cc] = hi;
                        Cs[base + N + cc] = lo;
                        Cs[base + 2 * (size_t)N + cc] = hi;
                    } else {
                        size_t off = (size_t)rr * N + cc;
                        if (RES) val += C[off];
                        C[off] = val;
                    }
                }
            }
        }
    }
}

// ---------------- fused flash attention (fp32, causal) ----------------
__global__ void __launch_bounds__(256) flash_kernel(const float* __restrict__ qkv,
                                                    __nv_bfloat16* __restrict__ ab) {
    extern __shared__ float fsm[];
    float* Qs = fsm;                   // [64][64]  (d-major)
    float* Ks = Qs + 64 * 64;          // [64][64]  (d-major)
    float* Vs = Ks + 64 * 64;          // [64][68]
    float* Ps = Vs + 64 * 68;          // [64][65]

    int br = gridDim.x - 1 - blockIdx.x;
    int h  = blockIdx.y;
    int tid = threadIdx.x;
    int tx = tid & 15, ty = tid >> 4;

    const float* qb = qkv + (size_t)br * 64 * (3 * DIM) + h * DH;
    #pragma unroll
    for (int l = 0; l < 4; l++) {
        int i = tid + l * 256;
        int r  = i >> 4;
        int d4 = (i & 15) * 4;
        float4 v = *(const float4*)(qb + (size_t)r * (3 * DIM) + d4);
        Qs[(d4 + 0) * 64 + r] = v.x * 0.125f;
        Qs[(d4 + 1) * 64 + r] = v.y * 0.125f;
        Qs[(d4 + 2) * 64 + r] = v.z * 0.125f;
        Qs[(d4 + 3) * 64 + r] = v.w * 0.125f;
    }

    float run_max[4], run_sum[4], O[4][4];
    #pragma unroll
    for (int r = 0; r < 4; r++) {
        run_max[r] = -FLT_MAX; run_sum[r] = 0.f;
        #pragma unroll
        for (int c = 0; c < 4; c++) O[r][c] = 0.f;
    }

    for (int kb = 0; kb <= br; kb++) {
        __syncthreads();
        const float* kbp = qkv + (size_t)kb * 64 * (3 * DIM) + (HEADS + h) * DH;
        const float* vbp = qkv + (size_t)kb * 64 * (3 * DIM) + (2 * HEADS + h) * DH;
        #pragma unroll
        for (int l = 0; l < 4; l++) {
            int i = tid + l * 256;
            int r  = i >> 4;
            int d4 = (i & 15) * 4;
            float4 w = *(const float4*)(kbp + (size_t)r * (3 * DIM) + d4);
            Ks[(d4 + 0) * 64 + r] = w.x; Ks[(d4 + 1) * 64 + r] = w.y;
            Ks[(d4 + 2) * 64 + r] = w.z; Ks[(d4 + 3) * 64 + r] = w.w;
            float4 u = *(const float4*)(vbp + (size_t)r * (3 * DIM) + d4);
            *(float4*)(Vs + r * 68 + d4) = u;
        }
        __syncthreads();

        float acc[4][4];
        #pragma unroll
        for (int r = 0; r < 4; r++)
            #pragma unroll
            for (int c = 0; c < 4; c++) acc[r][c] = 0.f;
        #pragma unroll 4
        for (int d = 0; d < 64; d++) {
            float4 rq = *(const float4*)(Qs + d * 64 + ty * 4);
            float4 rk = *(const float4*)(Ks + d * 64 + tx * 4);
            float qa[4] = {rq.x, rq.y, rq.z, rq.w};
            float ka[4] = {rk.x, rk.y, rk.z, rk.w};
            #pragma unroll
            for (int r = 0; r < 4; r++)
                #pragma unroll
                for (int c = 0; c < 4; c++)
                    acc[r][c] += qa[r] * ka[c];
        }

        if (kb == br) {
            #pragma unroll
            for (int r = 0; r < 4; r++) {
                int gi = ty * 4 + r;
                #pragma unroll
                for (int c = 0; c < 4; c++) {
                    int gj = tx * 4 + c;
                    if (gj > gi) acc[r][c] = -FLT_MAX;
                }
            }
        }

        float alpha[4];
        #pragma unroll
        for (int r = 0; r < 4; r++) {
            float mt = fmaxf(fmaxf(acc[r][0], acc[r][1]), fmaxf(acc[r][2], acc[r][3]));
            #pragma unroll
            for (int msk = 8; msk > 0; msk >>= 1)
                mt = fmaxf(mt, __shfl_xor_sync(0xffffffffu, mt, msk));
            float nm = fmaxf(run_max[r], mt);
            alpha[r] = expf(run_max[r] - nm);
            run_max[r] = nm;
            float ps = 0.f;
            #pragma unroll
            for (int c = 0; c < 4; c++) {
                float p = expf(acc[r][c] - nm);
                acc[r][c] = p;
                ps += p;
            }
            #pragma unroll
            for (int msk = 8; msk > 0; msk >>= 1)
                ps += __shfl_xor_sync(0xffffffffu, ps, msk);
            run_sum[r] = run_sum[r] * alpha[r] + ps;
        }

        #pragma unroll
        for (int r = 0; r < 4; r++)
            #pragma unroll
            for (int c = 0; c < 4; c++)
                Ps[(tx * 4 + c) * 65 + ty * 4 + r] = acc[r][c];
        __syncthreads();

        #pragma unroll
        for (int r = 0; r < 4; r++)
            #pragma unroll
            for (int c = 0; c < 4; c++) O[r][c] *= alpha[r];
        #pragma unroll 4
        for (int jj = 0; jj < 64; jj++) {
            float pr[4];
            #pragma unroll
            for (int r = 0; r < 4; r++) pr[r] = Ps[jj * 65 + ty * 4 + r];
            float4 rv = *(const float4*)(Vs + jj * 68 + tx * 4);
            float vv[4] = {rv.x, rv.y, rv.z, rv.w};
            #pragma unroll
            for (int r = 0; r < 4; r++)
                #pragma unroll
                for (int c = 0; c < 4; c++)
                    O[r][c] += pr[r] * vv[c];
        }
    }

    #pragma unroll
    for (int r = 0; r < 4; r++) {
        int gi = br * 64 + ty * 4 + r;
        float inv = 1.0f / run_sum[r];
        size_t base = (size_t)gi * (3 * DIM);
        #pragma unroll
        for (int c = 0; c < 4; c++) {
            int col = h * DH + tx * 4 + c;
            float v = O[r][c] * inv;
            __nv_bfloat16 hi = __float2bfloat16_rn(v);
            __nv_bfloat16 lo = __float2bfloat16_rn(v - __bfloat162float(hi));
            ab[base + col] = hi;
            ab[base + DIM + col] = lo;
            ab[base + 2 * DIM + col] = hi;
        }
    }
}

#define FLASH_SMEM ((64 * 64 + 64 * 64 + 64 * 68 + 64 * 65) * 4)

// ---------------- launch ----------------
static inline void convw(const float* src, __nv_bfloat16* dst, long long K, long long N) {
    long long KN4 = K * N / 4;
    convw_kernel<<<(unsigned)((KN4 + 255) / 256), 256>>>((const float4*)src, dst, KN4);
}

extern "C" void kernel_launch(void* const* d_in, const int* in_sizes, int n_in,
                              void* d_out, int out_size) {
    const int*   tokens      = (const int*)  d_in[0];
    const float* emb         = (const float*)d_in[1];
    const float* gamma_attn  = (const float*)d_in[2];
    const float* w_qkv       = (const float*)d_in[3];
    const float* w_out       = (const float*)d_in[4];
    const float* gamma_ff    = (const float*)d_in[5];
    const float* w_ff1       = (const float*)d_in[6];
    const float* b_ff1       = (const float*)d_in[7];
    const float* w_ff2       = (const float*)d_in[8];
    const float* b_ff2       = (const float*)d_in[9];
    const float* gamma_final = (const float*)d_in[10];
    const float* w_logits    = (const float*)d_in[11];
    float* out = (float*)d_out;

    float *x, *qkv;
    __nv_bfloat16 *ab, *ab2, *wb;
    cudaGetSymbolAddress((void**)&x,   g_x);
    cudaGetSymbolAddress((void**)&qkv, g_qkv);
    cudaGetSymbolAddress((void**)&ab,  g_ab);
    cudaGetSymbolAddress((void**)&ab2, g_ab2);
    cudaGetSymbolAddress((void**)&wb,  g_wb);

    cudaFuncSetAttribute(flash_kernel, cudaFuncAttributeMaxDynamicSharedMemorySize,
                         FLASH_SMEM);
    cudaFuncSetAttribute(bgemm_kernel<3, false, false, false, false, false>,
                         cudaFuncAttributeMaxDynamicSharedMemorySize, GEMM_SMEM);
    cudaFuncSetAttribute(bgemm_kernel<3, false, false, true, false, false>,
                         cudaFuncAttributeMaxDynamicSharedMemorySize, GEMM_SMEM);
    cudaFuncSetAttribute(bgemm_kernel<3, false, true, false, true, true>,
                         cudaFuncAttributeMaxDynamicSharedMemorySize, GEMM_SMEM);
    cudaFuncSetAttribute(bgemm_kernel<3, false, true, true, false, false>,
                         cudaFuncAttributeMaxDynamicSharedMemorySize, GEMM_SMEM);
    cudaFuncSetAttribute(bgemm_kernel<2, true, false, false, false, false>,
                         cudaFuncAttributeMaxDynamicSharedMemorySize, GEMM_SMEM);

    // launch order: index 3 = qkv bgemm (for ncu sampling)
    embed_kernel<<<SEQ * DIM / 256, 256>>>(tokens, emb, x);                        // 0
    convw(w_qkv, wb + WB_QKV(0), DIM, 3 * DIM);                                    // 1
    rmsnorm_split_kernel<<<SEQ, 256>>>(x, gamma_attn, ab);                         // 2

    for (int l = 0; l < DEPTH; l++) {
        if (l > 0) {
            convw(w_qkv + (size_t)l * DIM * 3 * DIM, wb + WB_QKV(l), DIM, 3 * DIM);
            rmsnorm_split_kernel<<<SEQ, 256>>>(x, gamma_attn + l * DIM, ab);
        }
        bgemm_kernel<3, false, false, false, false, false>
            <<<dim3(SEQ / 128, 3 * DIM / 128), 256, GEMM_SMEM>>>(
            ab, wb + WB_QKV(l), nullptr, qkv, nullptr, 3 * DIM, DIM / 64);         // l=0: 3
        rotary_kernel<<<SEQ * 1024 / 256, 256>>>(qkv);
        flash_kernel<<<dim3(SEQ / 64, HEADS), 256, FLASH_SMEM>>>(qkv, ab);
        convw(w_out + (size_t)l * DIM * DIM, wb + WB_OUT(l), DIM, DIM);
        bgemm_kernel<3, false, false, true, false, false>
            <<<dim3(SEQ / 128, DIM / 128), 256, GEMM_SMEM>>>(
            ab, wb + WB_OUT(l), nullptr, x, nullptr, DIM, DIM / 64);
        // --- feedforward block ---
        rmsnorm_split_kernel<<<SEQ, 256>>>(x, gamma_ff + l * DIM, ab);
        convw(w_ff1 + (size_t)l * DIM * FFD, wb + WB_FF1(l), DIM, FFD);
        bgemm_kernel<3, false, true, false, true, true>
            <<<dim3(SEQ / 128, FFD / 128), 256, GEMM_SMEM>>>(
            ab, wb + WB_FF1(l), b_ff1 + (size_t)l * FFD, nullptr, ab2, FFD, DIM / 64);
        convw(w_ff2 + (size_t)l * FFD * DIM, wb + WB_FF2(l), FFD, DIM);
        bgemm_kernel<3, false, true, true, false, false>
            <<<dim3(SEQ / 128, DIM / 128), 256, GEMM_SMEM>>>(
            ab2, wb + WB_FF2(l), b_ff2 + (size_t)l * DIM, x, nullptr, DIM, FFD / 64);
    }

    // final norm + fp16 2-term logits GEMM
    {
        long long KN4 = (long long)DIM * VOCAB / 4;
        convw_f16_kernel<<<(unsigned)((KN4 + 255) / 256), 256>>>(
            (const float4*)w_logits, (__half*)(wb + WB_LOGITS), KN4);
    }
    rmsnorm_split_f16_kernel<<<SEQ, 256>>>(x, gamma_final, (__half*)ab);
    bgemm_kernel<2, true, false, false, false, false>
        <<<dim3(SEQ / 128, VOCAB / 128), 256, GEMM_SMEM>>>(
        ab, wb + WB_LOGITS, nullptr, out, nullptr, VOCAB, DIM / 64);
}